// round 13
// baseline (speedup 1.0000x reference)
#include <cuda_runtime.h>
#include <cuda_bf16.h>
#include <cstdint>

#define H 128
#define MAXN 50000
#define NBUF ((size_t)MAXN * H)
#define MAXWORK 851968            // >= E + N

#define HP 132    // H-tile pitch (words): %32==4 -> A-frag LDS conflict-free
#define WP 136    // W pitch (words):     %32==8 -> B-frag LDS conflict-free
#define WTILE 16  // edges per warp-tile
#define EDGE_WARPS 5
#define EDGE_SMEM ((128 * WP + EDGE_WARPS * WTILE * HP) * 4)   // ~111.9KB -> 2 blocks/SM
#define NTM 32    // node tile M (double-buffered)
#define NODE_SMEM ((2 * 128 * WP + 2 * 2 * NTM * HP) * 4)      // ~206.8KB

// float scratch: X1, X2 (ping-pong), A, B (per-node partial GEMMs)
__device__ float4 g_scratch4[4 * NBUF / 4];
// int scratch: cnt[50048] | offs[50048] | sortedSrc[MAXWORK] | sortedDst[MAXWORK]
__device__ int g_iscratch[2 * 50048 + 2 * MAXWORK];

__device__ __forceinline__ void atomicMaxF(float* addr, float v) {
    if (v >= 0.f) atomicMax((int*)addr, __float_as_int(v));
    else          atomicMin((unsigned int*)addr, __float_as_uint(v));
}

__device__ __forceinline__ float tf32r(float x) {
    uint32_t u;
    asm("cvt.rna.tf32.f32 %0, %1;" : "=r"(u) : "f"(x));
    return __uint_as_float(u);
}

#define MMA_TF32(acc, a0, a1, a2, a3, b0, b1)                                   \
    asm("mma.sync.aligned.m16n8k8.row.col.f32.tf32.tf32.f32 "                   \
        "{%0,%1,%2,%3}, {%4,%5,%6,%7}, {%8,%9}, {%0,%1,%2,%3};"                 \
        : "+f"(acc[0]), "+f"(acc[1]), "+f"(acc[2]), "+f"(acc[3])                \
        : "r"(a0), "r"(a1), "r"(a2), "r"(a3), "r"(b0), "r"(b1))

// ---------------------------------------------------------------------------
// Sorting (counting sort by dst). Runs once per launch, reused by all layers.
// ---------------------------------------------------------------------------
__global__ void hist_kernel(const int* __restrict__ ei, int* __restrict__ cnt,
                            int nE, int nN)
{
    const int nwork = nE + nN;
    for (int e = blockIdx.x * blockDim.x + threadIdx.x; e < nwork;
         e += gridDim.x * blockDim.x) {
        const int d = (e < nE) ? ei[nE + e] : (e - nE);
        atomicAdd(&cnt[d], 1);
    }
}

__global__ void __launch_bounds__(1024) scan_kernel(
    const int* __restrict__ cnt, int* __restrict__ offs, int nN)
{
    __shared__ int sums[1024];
    const int t = threadIdx.x;
    const int chunk = (nN + 1023) / 1024;
    const int lo = t * chunk;
    const int hi = min(lo + chunk, nN);
    int s = 0;
    for (int i = lo; i < hi; i++) s += cnt[i];
    sums[t] = s;
    __syncthreads();
    for (int off = 1; off < 1024; off <<= 1) {
        int v = (t >= off) ? sums[t - off] : 0;
        __syncthreads();
        sums[t] += v;
        __syncthreads();
    }
    int run = sums[t] - s;   // exclusive prefix
    for (int i = lo; i < hi; i++) {
        offs[i] = run;
        run += cnt[i];
    }
}

__global__ void scatter_kernel(const int* __restrict__ ei, int* __restrict__ offs,
                               int* __restrict__ sSrc, int* __restrict__ sDst,
                               int nE, int nN)
{
    const int nwork = nE + nN;
    for (int e = blockIdx.x * blockDim.x + threadIdx.x; e < nwork;
         e += gridDim.x * blockDim.x) {
        int s, d;
        if (e < nE) { s = ei[e]; d = ei[nE + e]; }
        else        { s = d = e - nE; }
        const int pos = atomicAdd(&offs[d], 1);
        sSrc[pos] = s;
        sDst[pos] = d;
    }
}

// ---------------------------------------------------------------------------
// Node GEMM v2: tensor cores, 3xTF32 split, M=32 tiles, double-buffered X,
// next-tile LDG overlapped with current-tile MMA. 1 sync per tile.
// blockIdx.y==0: x@(W1a-W1b)+b1 -> A ; ==1: x@W1b -> Bm
// 8 warps: mg=wid>>2 (m16 band), ng=wid&3 (n32 band).
// ---------------------------------------------------------------------------
__global__ void __launch_bounds__(256) node_mma_kernel(
    const float* __restrict__ x, const float* __restrict__ W1l,
    const float* __restrict__ b1l, float* __restrict__ A, float* __restrict__ Bm,
    int nN)
{
    extern __shared__ float sm[];
    float* Wh = sm;                       // [128][WP]
    float* Wl = sm + 128 * WP;            // [128][WP]
    float* Xb = sm + 2 * 128 * WP;        // 2 x ( Xh[32][HP], Xl[32][HP] )

    const int tid  = threadIdx.x;
    const int lane = tid & 31;
    const int wid  = tid >> 5;
    const int mg   = wid >> 2;      // 0..1 : rows 16*mg..16*mg+15
    const int ng   = wid & 3;       // 0..3 : cols 32*ng..
    const int lr   = lane >> 2;     // 0..7
    const int lc   = lane & 3;      // 0..3
    const int half = blockIdx.y;

    for (int i = tid; i < 128 * 128; i += 256) {
        const int k = i >> 7, j = i & 127;
        float wv = (half == 0)
            ? (W1l[k * H + j] - W1l[(H + k) * H + j])
            : W1l[(H + k) * H + j];
        const float hi = tf32r(wv);
        Wh[k * WP + j] = hi;
        Wl[k * WP + j] = tf32r(wv - hi);
    }

    float2 b1c[4];
    #pragma unroll
    for (int ni = 0; ni < 4; ni++) {
        if (half == 0) b1c[ni] = *(const float2*)(b1l + 32 * ng + 8 * ni + 2 * lc);
        else           b1c[ni] = make_float2(0.f, 0.f);
    }
    float* outP = (half == 0) ? A : Bm;

    // loader mapping: thread loads 4 rows' worth: row = (tid>>5)*4+k, col4 = tid&31
    const int ldRow0 = (tid >> 5) * 4;
    const int ldCol4 = (tid & 31) * 4;

    const int ntiles = (nN + NTM - 1) / NTM;

    // ---- preload tile 0 ----
    int tile = blockIdx.x;
    {
        float* Xh = Xb;                 // buffer 0
        float* Xl = Xb + NTM * HP;
        #pragma unroll
        for (int k = 0; k < 4; k++) {
            const int r = ldRow0 + k;
            const int n = tile * NTM + r;
            float4 v = (tile < ntiles && n < nN)
                ? *(const float4*)(x + (size_t)n * H + ldCol4)
                : make_float4(0.f, 0.f, 0.f, 0.f);
            float4 hi4, lo4;
            hi4.x = tf32r(v.x); lo4.x = tf32r(v.x - hi4.x);
            hi4.y = tf32r(v.y); lo4.y = tf32r(v.y - hi4.y);
            hi4.z = tf32r(v.z); lo4.z = tf32r(v.z - hi4.z);
            hi4.w = tf32r(v.w); lo4.w = tf32r(v.w - hi4.w);
            *(float4*)(Xh + r * HP + ldCol4) = hi4;
            *(float4*)(Xl + r * HP + ldCol4) = lo4;
        }
    }
    __syncthreads();

    int cur = 0;
    for (; tile < ntiles; ) {
        const int nt = tile + gridDim.x;

        // ---- issue next tile's LDGs (latency overlaps MMA below) ----
        float4 vn[4];
        if (nt < ntiles) {
            #pragma unroll
            for (int k = 0; k < 4; k++) {
                const int n = nt * NTM + ldRow0 + k;
                vn[k] = (n < nN)
                    ? *(const float4*)(x + (size_t)n * H + ldCol4)
                    : make_float4(0.f, 0.f, 0.f, 0.f);
            }
        }

        // ---- mma from buf[cur] ----
        const float* Xh = Xb + cur * (2 * NTM * HP);
        const float* Xl = Xh + NTM * HP;
        float acc[4][4];
        #pragma unroll
        for (int ni = 0; ni < 4; ni++)
            #pragma unroll
            for (int c = 0; c < 4; c++) acc[ni][c] = 0.f;

        #pragma unroll
        for (int ks = 0; ks < 16; ks++) {
            const int kb = ks * 8;
            const int ro = (16 * mg + lr) * HP + kb + lc;
            const uint32_t ah0 = __float_as_uint(Xh[ro]);
            const uint32_t ah1 = __float_as_uint(Xh[ro + 8 * HP]);
            const uint32_t ah2 = __float_as_uint(Xh[ro + 4]);
            const uint32_t ah3 = __float_as_uint(Xh[ro + 8 * HP + 4]);
            const uint32_t al0 = __float_as_uint(Xl[ro]);
            const uint32_t al1 = __float_as_uint(Xl[ro + 8 * HP]);
            const uint32_t al2 = __float_as_uint(Xl[ro + 4]);
            const uint32_t al3 = __float_as_uint(Xl[ro + 8 * HP + 4]);
            #pragma unroll
            for (int ni = 0; ni < 4; ni++) {
                const int bo = (kb + lc) * WP + 32 * ng + 8 * ni + lr;
                const uint32_t bh0 = __float_as_uint(Wh[bo]);
                const uint32_t bh1 = __float_as_uint(Wh[bo + 4 * WP]);
                const uint32_t bl0 = __float_as_uint(Wl[bo]);
                const uint32_t bl1 = __float_as_uint(Wl[bo + 4 * WP]);
                MMA_TF32(acc[ni], ah0, ah1, ah2, ah3, bh0, bh1);
                MMA_TF32(acc[ni], al0, al1, al2, al3, bh0, bh1);
                MMA_TF32(acc[ni], ah0, ah1, ah2, ah3, bl0, bl1);
            }
        }

        // ---- store outputs for this tile ----
        {
            const int r0 = 16 * mg + lr;
            const int n0 = tile * NTM;
            #pragma unroll
            for (int ni = 0; ni < 4; ni++) {
                const int col = 32 * ng + 8 * ni + 2 * lc;
                if (n0 + r0 < nN)
                    *(float2*)(outP + (size_t)(n0 + r0) * H + col) =
                        make_float2(acc[ni][0] + b1c[ni].x, acc[ni][1] + b1c[ni].y);
                if (n0 + r0 + 8 < nN)
                    *(float2*)(outP + (size_t)(n0 + r0 + 8) * H + col) =
                        make_float2(acc[ni][2] + b1c[ni].x, acc[ni][3] + b1c[ni].y);
            }
        }

        // ---- split+store next tile into buf[cur^1] ----
        if (nt < ntiles) {
            float* XhN = Xb + (cur ^ 1) * (2 * NTM * HP);
            float* XlN = XhN + NTM * HP;
            #pragma unroll
            for (int k = 0; k < 4; k++) {
                const int r = ldRow0 + k;
                float4 hi4, lo4;
                hi4.x = tf32r(vn[k].x); lo4.x = tf32r(vn[k].x - hi4.x);
                hi4.y = tf32r(vn[k].y); lo4.y = tf32r(vn[k].y - hi4.y);
                hi4.z = tf32r(vn[k].z); lo4.z = tf32r(vn[k].z - hi4.z);
                hi4.w = tf32r(vn[k].w); lo4.w = tf32r(vn[k].w - hi4.w);
                *(float4*)(XhN + r * HP + ldCol4) = hi4;
                *(float4*)(XlN + r * HP + ldCol4) = lo4;
            }
        }
        __syncthreads();   // buf[cur^1] ready; all reads of buf[cur] done
        cur ^= 1;
        tile = nt;
    }
}

// ---------------------------------------------------------------------------
// Edge kernel (R10 shape + 5th warp): warp-independent 16-edge tiles,
// 160-thread blocks (5 warps), 2 blocks/SM, shared W2s. No block barriers
// in the loop.
// ---------------------------------------------------------------------------
__global__ void __launch_bounds__(160) edge_mma_kernel(
    const float* __restrict__ A, const float* __restrict__ Bm,
    const float* __restrict__ W2, const float* __restrict__ b2,
    const int* __restrict__ sSrc, const int* __restrict__ sDst,
    float* __restrict__ y, int nwork)
{
    extern __shared__ float sm[];
    float* W2s = sm;                                // [128][WP]
    const int tid  = threadIdx.x;
    const int lane = tid & 31;
    const int wid  = tid >> 5;                      // 0..4
    float* Hs = sm + 128 * WP + wid * (WTILE * HP); // per-warp [16][HP]

    // Co-op load W2 (tf32-rounded) into pitch-WP layout
    for (int i = tid; i < 128 * 32; i += 160) {
        const int k = i >> 5, j = i & 31;
        float4 w = *(const float4*)(W2 + k * H + j * 4);
        w.x = tf32r(w.x); w.y = tf32r(w.y); w.z = tf32r(w.z); w.w = tf32r(w.w);
        *(float4*)(W2s + k * WP + j * 4) = w;
    }
    const float4 b2c = *(const float4*)(b2 + lane * 4);
    __syncthreads();   // only barrier: W2s ready

    const int lr   = lane >> 2;     // 0..7
    const int lc   = lane & 3;      // 0..3
    const int eL   = lane >> 1;     // 0..15 : my build row
    const int half = lane & 1;      // 0..1  : column half

    const int ntiles = (nwork + WTILE - 1) / WTILE;
    const int gw     = blockIdx.x * EDGE_WARPS + wid;
    const int stride = gridDim.x * EDGE_WARPS;

    for (int tile = gw; tile < ntiles; tile += stride) {
        const int e0 = tile * WTILE;

        // ---- build: lane = (row eL, half) -> 64 cols ----
        int s = -1, d = -1;
        {
            const int e = e0 + eL;
            if (e < nwork) { s = sSrc[e]; d = sDst[e]; }
            float* hrow = Hs + eL * HP + half * 64;
            if (d >= 0) {
                const float4* ap = (const float4*)(A  + (size_t)d * H + half * 64);
                const float4* bp = (const float4*)(Bm + (size_t)s * H + half * 64);
                #pragma unroll
                for (int i = 0; i < 16; i++) {
                    const float4 a = ap[i], b = bp[i];
                    float4 hh;
                    hh.x = tf32r(fmaxf(a.x + b.x, 0.f));
                    hh.y = tf32r(fmaxf(a.y + b.y, 0.f));
                    hh.z = tf32r(fmaxf(a.z + b.z, 0.f));
                    hh.w = tf32r(fmaxf(a.w + b.w, 0.f));
                    *(float4*)(hrow + i * 4) = hh;
                }
            } else {
                #pragma unroll
                for (int i = 0; i < 16; i++)
                    *(float4*)(hrow + i * 4) = make_float4(0.f, 0.f, 0.f, 0.f);
            }
        }
        __syncwarp();

        // ---- mma: m16 (rows 0..15) x n128 x k128 ----
        float acc[16][4];
        #pragma unroll
        for (int ni = 0; ni < 16; ni++)
            #pragma unroll
            for (int c = 0; c < 4; c++) acc[ni][c] = 0.f;

        #pragma unroll
        for (int ks = 0; ks < 16; ks++) {
            const int kb = ks * 8;
            const float* ab = Hs + lr * HP + kb + lc;
            const uint32_t a0 = __float_as_uint(ab[0]);
            const uint32_t a1 = __float_as_uint(ab[8 * HP]);
            const uint32_t a2 = __float_as_uint(ab[4]);
            const uint32_t a3 = __float_as_uint(ab[8 * HP + 4]);
            #pragma unroll
            for (int ni = 0; ni < 16; ni++) {
                const float* bb = W2s + (kb + lc) * WP + 8 * ni + lr;
                const uint32_t b0 = __float_as_uint(bb[0]);
                const uint32_t b1 = __float_as_uint(bb[4 * WP]);
                MMA_TF32(acc[ni], a0, a1, a2, a3, b0, b1);
            }
        }
        __syncwarp();   // frag reads done before writeback overwrites Hs

        // ---- writeback raw acc into Hs ----
        #pragma unroll
        for (int ni = 0; ni < 16; ni++) {
            const int col = 8 * ni + 2 * lc;
            *(float2*)(Hs + lr * HP + col)       = make_float2(acc[ni][0], acc[ni][1]);
            *(float2*)(Hs + (lr + 8) * HP + col) = make_float2(acc[ni][2], acc[ni][3]);
        }
        __syncwarp();

        // ---- segmented max over 16 sorted rows; lane = 4 cols; b2 folded ----
        {
            int cur_d = -1;
            float4 m = make_float4(0.f, 0.f, 0.f, 0.f);
            #pragma unroll
            for (int r = 0; r < 16; r++) {
                const int dr = __shfl_sync(0xFFFFFFFFu, d, 2 * r);
                const float4 v = *(const float4*)(Hs + r * HP + lane * 4);
                if (dr != cur_d) {
                    if (cur_d >= 0) {
                        float* yr = y + (size_t)cur_d * H + lane * 4;
                        atomicMaxF(yr + 0, m.x + b2c.x);
                        atomicMaxF(yr + 1, m.y + b2c.y);
                        atomicMaxF(yr + 2, m.z + b2c.z);
                        atomicMaxF(yr + 3, m.w + b2c.w);
                    }
                    cur_d = dr;
                    m = v;
                } else {
                    m.x = fmaxf(m.x, v.x); m.y = fmaxf(m.y, v.y);
                    m.z = fmaxf(m.z, v.z); m.w = fmaxf(m.w, v.w);
                }
            }
            if (cur_d >= 0) {
                float* yr = y + (size_t)cur_d * H + lane * 4;
                atomicMaxF(yr + 0, m.x + b2c.x);
                atomicMaxF(yr + 1, m.y + b2c.y);
                atomicMaxF(yr + 2, m.z + b2c.z);
                atomicMaxF(yr + 3, m.w + b2c.w);
            }
        }
        __syncwarp();   // reduce reads done before next build overwrites Hs
    }
}

// ---------------------------------------------------------------------------
// Final: out[n] = x[n] @ Wf + bf   (H=128 -> D=3). Warp per node.
// ---------------------------------------------------------------------------
__global__ void __launch_bounds__(256) final_kernel(
    const float* __restrict__ x, const float* __restrict__ Wf,
    const float* __restrict__ bf, float* __restrict__ out, int nN)
{
    __shared__ float Wfs[H * 3];
    const int tid = threadIdx.x;
    for (int i = tid; i < H * 3; i += 256) Wfs[i] = Wf[i];
    __syncthreads();

    const int lane = tid & 31;
    const int node = blockIdx.x * 8 + (tid >> 5);
    if (node >= nN) return;

    const float4 xv = *(const float4*)(x + (size_t)node * H + lane * 4);
    float s0 = 0.f, s1 = 0.f, s2 = 0.f;
    const float xt[4] = {xv.x, xv.y, xv.z, xv.w};
    #pragma unroll
    for (int t = 0; t < 4; t++) {
        const int k = lane * 4 + t;
        s0 = fmaf(xt[t], Wfs[k * 3 + 0], s0);
        s1 = fmaf(xt[t], Wfs[k * 3 + 1], s1);
        s2 = fmaf(xt[t], Wfs[k * 3 + 2], s2);
    }
    #pragma unroll
    for (int off = 16; off > 0; off >>= 1) {
        s0 += __shfl_down_sync(0xFFFFFFFFu, s0, off);
        s1 += __shfl_down_sync(0xFFFFFFFFu, s1, off);
        s2 += __shfl_down_sync(0xFFFFFFFFu, s2, off);
    }
    if (lane == 0) {
        out[(size_t)node * 3 + 0] = s0 + bf[0];
        out[(size_t)node * 3 + 1] = s1 + bf[1];
        out[(size_t)node * 3 + 2] = s2 + bf[2];
    }
}

// ---------------------------------------------------------------------------
extern "C" void kernel_launch(void* const* d_in, const int* in_sizes, int n_in,
                              void* d_out, int out_size)
{
    const float*      x_in = (const float*)d_in[0];
    const int*        ei   = (const int*)d_in[1];
    const float*      W1   = (const float*)d_in[2];
    const float*      b1   = (const float*)d_in[3];
    const float*      W2   = (const float*)d_in[4];
    const float*      b2   = (const float*)d_in[5];
    const float*      Wf   = (const float*)d_in[6];
    const float*      bf   = (const float*)d_in[7];
    float*            out  = (float*)d_out;

    const int nN = in_sizes[0] / H;          // 50000
    const int nE = in_sizes[1] / 2;          // 800000
    const int L  = in_sizes[3] / H;          // 4
    const int nwork = nE + nN;

    void* base = nullptr;
    cudaGetSymbolAddress(&base, g_scratch4);
    float* X1 = (float*)base;
    float* X2 = X1 + NBUF;
    float* A  = X1 + 2 * NBUF;
    float* Bm = X1 + 3 * NBUF;

    void* ibase = nullptr;
    cudaGetSymbolAddress(&ibase, g_iscratch);
    int* cnt  = (int*)ibase;
    int* offs = cnt + 50048;
    int* sSrc = cnt + 2 * 50048;
    int* sDst = sSrc + MAXWORK;

    cudaFuncSetAttribute(edge_mma_kernel, cudaFuncAttributeMaxDynamicSharedMemorySize, EDGE_SMEM);
    cudaFuncSetAttribute(node_mma_kernel, cudaFuncAttributeMaxDynamicSharedMemorySize, NODE_SMEM);

    // ---- sort edges by dst (once; reused by all layers) ----
    cudaMemsetAsync(cnt, 0, 50048 * sizeof(int), 0);
    hist_kernel<<<592, 256>>>(ei, cnt, nE, nN);
    scan_kernel<<<1, 1024>>>(cnt, offs, nN);
    scatter_kernel<<<592, 256>>>(ei, offs, sSrc, sDst, nE, nN);

    float* bufs[2] = {X1, X2};

    const float* cur = x_in;
    for (int l = 0; l < L; l++) {
        node_mma_kernel<<<dim3(74, 2), 256, NODE_SMEM>>>(
            cur, W1 + (size_t)l * 2 * H * H, b1 + (size_t)l * H, A, Bm, nN);
        float* y = bufs[l & 1];
        cudaMemsetAsync(y, 0xFF, (size_t)nN * H * sizeof(float), 0);  // NaN init
        edge_mma_kernel<<<148 * 2, 160, EDGE_SMEM>>>(
            A, Bm, W2 + (size_t)l * H * H, b2 + (size_t)l * H, sSrc, sDst, y, nwork);
        cur = y;
    }
    final_kernel<<<(nN + 7) / 8, 256>>>(cur, Wf, bf, out, nN);
}

// round 14
// speedup vs baseline: 1.1046x; 1.1046x over previous
#include <cuda_runtime.h>
#include <cuda_bf16.h>
#include <cstdint>

#define H 128
#define MAXN 50000
#define NBUF ((size_t)MAXN * H)
#define MAXWORK 851968            // >= E + N

#define HP 132    // H-tile pitch (words): %32==4 -> A-frag LDS conflict-free
#define WP 136    // W pitch (words) for node kernel: %32==8 -> B-frag conflict-free
#define WPP 264   // paired-W2 pitch (words per (ks,lc) row): %32==8 -> LDS.64 conflict-free
#define WTILE 16  // edges per warp-tile
#define EDGE_WARPS 4
#define W2P_WORDS (16 * 4 * WPP)                               // 16896 words = 67.6KB
#define EDGE_SMEM ((W2P_WORDS + EDGE_WARPS * WTILE * HP) * 4)  // ~101.4KB -> 2 blocks/SM
#define NODE_SMEM ((2 * 128 * WP + 2 * 64 * HP) * 4)           // ~206.8KB

// float scratch: X1, X2 (ping-pong), A, B (per-node partial GEMMs)
__device__ float4 g_scratch4[4 * NBUF / 4];
// int scratch: cnt[50048] | offs[50048] | sortedSrc[MAXWORK] | sortedDst[MAXWORK]
__device__ int g_iscratch[2 * 50048 + 2 * MAXWORK];

__device__ __forceinline__ void atomicMaxF(float* addr, float v) {
    if (v >= 0.f) atomicMax((int*)addr, __float_as_int(v));
    else          atomicMin((unsigned int*)addr, __float_as_uint(v));
}

__device__ __forceinline__ float tf32r(float x) {
    uint32_t u;
    asm("cvt.rna.tf32.f32 %0, %1;" : "=r"(u) : "f"(x));
    return __uint_as_float(u);
}

#define MMA_TF32(acc, a0, a1, a2, a3, b0, b1)                                   \
    asm("mma.sync.aligned.m16n8k8.row.col.f32.tf32.tf32.f32 "                   \
        "{%0,%1,%2,%3}, {%4,%5,%6,%7}, {%8,%9}, {%0,%1,%2,%3};"                 \
        : "+f"(acc[0]), "+f"(acc[1]), "+f"(acc[2]), "+f"(acc[3])                \
        : "r"(a0), "r"(a1), "r"(a2), "r"(a3), "r"(b0), "r"(b1))

// ---------------------------------------------------------------------------
// Sorting (counting sort by dst). Runs once per launch, reused by all layers.
// ---------------------------------------------------------------------------
__global__ void hist_kernel(const int* __restrict__ ei, int* __restrict__ cnt,
                            int nE, int nN)
{
    const int nwork = nE + nN;
    for (int e = blockIdx.x * blockDim.x + threadIdx.x; e < nwork;
         e += gridDim.x * blockDim.x) {
        const int d = (e < nE) ? ei[nE + e] : (e - nE);
        atomicAdd(&cnt[d], 1);
    }
}

__global__ void __launch_bounds__(1024) scan_kernel(
    const int* __restrict__ cnt, int* __restrict__ offs, int nN)
{
    __shared__ int sums[1024];
    const int t = threadIdx.x;
    const int chunk = (nN + 1023) / 1024;
    const int lo = t * chunk;
    const int hi = min(lo + chunk, nN);
    int s = 0;
    for (int i = lo; i < hi; i++) s += cnt[i];
    sums[t] = s;
    __syncthreads();
    for (int off = 1; off < 1024; off <<= 1) {
        int v = (t >= off) ? sums[t - off] : 0;
        __syncthreads();
        sums[t] += v;
        __syncthreads();
    }
    int run = sums[t] - s;   // exclusive prefix
    for (int i = lo; i < hi; i++) {
        offs[i] = run;
        run += cnt[i];
    }
}

__global__ void scatter_kernel(const int* __restrict__ ei, int* __restrict__ offs,
                               int* __restrict__ sSrc, int* __restrict__ sDst,
                               int nE, int nN)
{
    const int nwork = nE + nN;
    for (int e = blockIdx.x * blockDim.x + threadIdx.x; e < nwork;
         e += gridDim.x * blockDim.x) {
        int s, d;
        if (e < nE) { s = ei[e]; d = ei[nE + e]; }
        else        { s = d = e - nE; }
        const int pos = atomicAdd(&offs[d], 1);
        sSrc[pos] = s;
        sDst[pos] = d;
    }
}

// ---------------------------------------------------------------------------
// Node GEMM via tensor cores, 3xTF32 split (fp32-accurate). R10 version.
// ---------------------------------------------------------------------------
__global__ void __launch_bounds__(256) node_mma_kernel(
    const float* __restrict__ x, const float* __restrict__ W1l,
    const float* __restrict__ b1l, float* __restrict__ A, float* __restrict__ Bm,
    int nN)
{
    extern __shared__ float sm[];
    float* Wh = sm;                  // [128][WP]
    float* Wl = sm + 128 * WP;       // [128][WP]
    float* Xh = sm + 2 * 128 * WP;   // [64][HP]
    float* Xl = Xh + 64 * HP;        // [64][HP]

    const int tid  = threadIdx.x;
    const int lane = tid & 31;
    const int wid  = tid >> 5;
    const int mg   = wid >> 2;      // 0..1
    const int ng   = wid & 3;       // 0..3
    const int lr   = lane >> 2;     // 0..7
    const int lc   = lane & 3;      // 0..3
    const int half = blockIdx.y;

    for (int i = tid; i < 128 * 128; i += 256) {
        const int k = i >> 7, j = i & 127;
        float wv = (half == 0)
            ? (W1l[k * H + j] - W1l[(H + k) * H + j])
            : W1l[(H + k) * H + j];
        const float hi = tf32r(wv);
        Wh[k * WP + j] = hi;
        Wl[k * WP + j] = tf32r(wv - hi);
    }

    float2 b1c[4];
    #pragma unroll
    for (int ni = 0; ni < 4; ni++) {
        if (half == 0) b1c[ni] = *(const float2*)(b1l + 32 * ng + 8 * ni + 2 * lc);
        else           b1c[ni] = make_float2(0.f, 0.f);
    }
    float* outP = (half == 0) ? A : Bm;
    __syncthreads();

    const int ntiles = (nN + 63) / 64;
    for (int tile = blockIdx.x; tile < ntiles; tile += gridDim.x) {
        const int n0 = tile * 64;

        for (int i = tid; i < 64 * 32; i += 256) {
            const int r = i >> 5, j4 = (i & 31) * 4;
            float4 v = (n0 + r < nN)
                ? *(const float4*)(x + (size_t)(n0 + r) * H + j4)
                : make_float4(0.f, 0.f, 0.f, 0.f);
            float4 hi4, lo4;
            hi4.x = tf32r(v.x); lo4.x = tf32r(v.x - hi4.x);
            hi4.y = tf32r(v.y); lo4.y = tf32r(v.y - hi4.y);
            hi4.z = tf32r(v.z); lo4.z = tf32r(v.z - hi4.z);
            hi4.w = tf32r(v.w); lo4.w = tf32r(v.w - hi4.w);
            *(float4*)(Xh + r * HP + j4) = hi4;
            *(float4*)(Xl + r * HP + j4) = lo4;
        }
        __syncthreads();

        float acc[2][4][4];
        #pragma unroll
        for (int mi = 0; mi < 2; mi++)
            #pragma unroll
            for (int ni = 0; ni < 4; ni++)
                #pragma unroll
                for (int c = 0; c < 4; c++) acc[mi][ni][c] = 0.f;

        #pragma unroll
        for (int ks = 0; ks < 16; ks++) {
            const int kb = ks * 8;
            uint32_t ah[2][4], al[2][4];
            #pragma unroll
            for (int mi = 0; mi < 2; mi++) {
                const int ro = (32 * mg + 16 * mi + lr) * HP + kb + lc;
                ah[mi][0] = __float_as_uint(Xh[ro]);
                ah[mi][1] = __float_as_uint(Xh[ro + 8 * HP]);
                ah[mi][2] = __float_as_uint(Xh[ro + 4]);
                ah[mi][3] = __float_as_uint(Xh[ro + 8 * HP + 4]);
                al[mi][0] = __float_as_uint(Xl[ro]);
                al[mi][1] = __float_as_uint(Xl[ro + 8 * HP]);
                al[mi][2] = __float_as_uint(Xl[ro + 4]);
                al[mi][3] = __float_as_uint(Xl[ro + 8 * HP + 4]);
            }
            #pragma unroll
            for (int ni = 0; ni < 4; ni++) {
                const int bo = (kb + lc) * WP + 32 * ng + 8 * ni + lr;
                const uint32_t bh0 = __float_as_uint(Wh[bo]);
                const uint32_t bh1 = __float_as_uint(Wh[bo + 4 * WP]);
                const uint32_t bl0 = __float_as_uint(Wl[bo]);
                const uint32_t bl1 = __float_as_uint(Wl[bo + 4 * WP]);
                #pragma unroll
                for (int mi = 0; mi < 2; mi++) {
                    MMA_TF32(acc[mi][ni], ah[mi][0], ah[mi][1], ah[mi][2], ah[mi][3], bh0, bh1);
                    MMA_TF32(acc[mi][ni], al[mi][0], al[mi][1], al[mi][2], al[mi][3], bh0, bh1);
                    MMA_TF32(acc[mi][ni], ah[mi][0], ah[mi][1], ah[mi][2], ah[mi][3], bl0, bl1);
                }
            }
        }
        __syncthreads();

        #pragma unroll
        for (int mi = 0; mi < 2; mi++) {
            const int r0 = 32 * mg + 16 * mi + lr;
            #pragma unroll
            for (int ni = 0; ni < 4; ni++) {
                const int col = 32 * ng + 8 * ni + 2 * lc;
                if (n0 + r0 < nN)
                    *(float2*)(outP + (size_t)(n0 + r0) * H + col) =
                        make_float2(acc[mi][ni][0] + b1c[ni].x, acc[mi][ni][1] + b1c[ni].y);
                if (n0 + r0 + 8 < nN)
                    *(float2*)(outP + (size_t)(n0 + r0 + 8) * H + col) =
                        make_float2(acc[mi][ni][2] + b1c[ni].x, acc[mi][ni][3] + b1c[ni].y);
            }
        }
    }
}

// ---------------------------------------------------------------------------
// Edge kernel (R10 + paired-k W2 layout): warp-independent 16-edge tiles,
// 128-thread blocks (4 warps), 2 blocks/SM. B fragments via single LDS.64.
// No __syncthreads in loop.
// ---------------------------------------------------------------------------
__global__ void __launch_bounds__(128, 2) edge_mma_kernel(
    const float* __restrict__ A, const float* __restrict__ Bm,
    const float* __restrict__ W2, const float* __restrict__ b2,
    const int* __restrict__ sSrc, const int* __restrict__ sDst,
    float* __restrict__ y, int nwork)
{
    extern __shared__ float sm[];
    float* W2p = sm;                               // [16*4][WPP]: (ks,lc) -> 128 float2
    const int tid  = threadIdx.x;
    const int lane = tid & 31;
    const int wid  = tid >> 5;
    float* Hs = sm + W2P_WORDS + wid * (WTILE * HP); // per-warp [16][HP]

    // Co-op load W2 into paired layout:
    //   W2p[(ks*4+lc)*WPP + 2*col] = ( tf32(W2[8ks+lc][col]), tf32(W2[8ks+lc+4][col]) )
    for (int i = tid; i < 64 * 128; i += 128) {
        const int pr  = i >> 7;        // 0..63 = ks*4+lc
        const int col = i & 127;
        const int k   = (pr >> 2) * 8 + (pr & 3);
        const float v0 = tf32r(W2[k * H + col]);
        const float v1 = tf32r(W2[(k + 4) * H + col]);
        *(float2*)(W2p + pr * WPP + 2 * col) = make_float2(v0, v1);
    }
    const float4 b2c = *(const float4*)(b2 + lane * 4);
    __syncthreads();   // only barrier: W2p ready

    const int lr   = lane >> 2;     // 0..7
    const int lc   = lane & 3;      // 0..3
    const int eL   = lane >> 1;     // 0..15 : my build row
    const int half = lane & 1;      // 0..1  : column half

    const int ntiles = (nwork + WTILE - 1) / WTILE;
    const int gw     = blockIdx.x * EDGE_WARPS + wid;
    const int stride = gridDim.x * EDGE_WARPS;

    for (int tile = gw; tile < ntiles; tile += stride) {
        const int e0 = tile * WTILE;

        // ---- build: lane = (row eL, half) -> 64 cols ----
        int s = -1, d = -1;
        {
            const int e = e0 + eL;
            if (e < nwork) { s = sSrc[e]; d = sDst[e]; }
            float* hrow = Hs + eL * HP + half * 64;
            if (d >= 0) {
                const float4* ap = (const float4*)(A  + (size_t)d * H + half * 64);
                const float4* bp = (const float4*)(Bm + (size_t)s * H + half * 64);
                #pragma unroll
                for (int i = 0; i < 16; i++) {
                    const float4 a = ap[i], b = bp[i];
                    float4 hh;
                    hh.x = tf32r(fmaxf(a.x + b.x, 0.f));
                    hh.y = tf32r(fmaxf(a.y + b.y, 0.f));
                    hh.z = tf32r(fmaxf(a.z + b.z, 0.f));
                    hh.w = tf32r(fmaxf(a.w + b.w, 0.f));
                    *(float4*)(hrow + i * 4) = hh;
                }
            } else {
                #pragma unroll
                for (int i = 0; i < 16; i++)
                    *(float4*)(hrow + i * 4) = make_float4(0.f, 0.f, 0.f, 0.f);
            }
        }
        __syncwarp();

        // ---- mma: m16 (rows 0..15) x n128 x k128 ----
        float acc[16][4];
        #pragma unroll
        for (int ni = 0; ni < 16; ni++)
            #pragma unroll
            for (int c = 0; c < 4; c++) acc[ni][c] = 0.f;

        #pragma unroll
        for (int ks = 0; ks < 16; ks++) {
            const int kb = ks * 8;
            const float* ab = Hs + lr * HP + kb + lc;
            const uint32_t a0 = __float_as_uint(ab[0]);
            const uint32_t a1 = __float_as_uint(ab[8 * HP]);
            const uint32_t a2 = __float_as_uint(ab[4]);
            const uint32_t a3 = __float_as_uint(ab[8 * HP + 4]);
            const float* bbase = W2p + (ks * 4 + lc) * WPP + 2 * lr;
            #pragma unroll
            for (int ni = 0; ni < 16; ni++) {
                const float2 bp = *(const float2*)(bbase + 16 * ni);
                MMA_TF32(acc[ni], a0, a1, a2, a3,
                         __float_as_uint(bp.x), __float_as_uint(bp.y));
            }
        }
        __syncwarp();   // frag reads done before writeback overwrites Hs

        // ---- writeback raw acc into Hs ----
        #pragma unroll
        for (int ni = 0; ni < 16; ni++) {
            const int col = 8 * ni + 2 * lc;
            *(float2*)(Hs + lr * HP + col)       = make_float2(acc[ni][0], acc[ni][1]);
            *(float2*)(Hs + (lr + 8) * HP + col) = make_float2(acc[ni][2], acc[ni][3]);
        }
        __syncwarp();

        // ---- segmented max over 16 sorted rows; lane = 4 cols; b2 folded ----
        {
            int cur_d = -1;
            float4 m = make_float4(0.f, 0.f, 0.f, 0.f);
            #pragma unroll
            for (int r = 0; r < 16; r++) {
                const int dr = __shfl_sync(0xFFFFFFFFu, d, 2 * r);
                const float4 v = *(const float4*)(Hs + r * HP + lane * 4);
                if (dr != cur_d) {
                    if (cur_d >= 0) {
                        float* yr = y + (size_t)cur_d * H + lane * 4;
                        atomicMaxF(yr + 0, m.x + b2c.x);
                        atomicMaxF(yr + 1, m.y + b2c.y);
                        atomicMaxF(yr + 2, m.z + b2c.z);
                        atomicMaxF(yr + 3, m.w + b2c.w);
                    }
                    cur_d = dr;
                    m = v;
                } else {
                    m.x = fmaxf(m.x, v.x); m.y = fmaxf(m.y, v.y);
                    m.z = fmaxf(m.z, v.z); m.w = fmaxf(m.w, v.w);
                }
            }
            if (cur_d >= 0) {
                float* yr = y + (size_t)cur_d * H + lane * 4;
                atomicMaxF(yr + 0, m.x + b2c.x);
                atomicMaxF(yr + 1, m.y + b2c.y);
                atomicMaxF(yr + 2, m.z + b2c.z);
                atomicMaxF(yr + 3, m.w + b2c.w);
            }
        }
        __syncwarp();   // reduce reads done before next build overwrites Hs
    }
}

// ---------------------------------------------------------------------------
// Final: out[n] = x[n] @ Wf + bf   (H=128 -> D=3). Warp per node.
// ---------------------------------------------------------------------------
__global__ void __launch_bounds__(256) final_kernel(
    const float* __restrict__ x, const float* __restrict__ Wf,
    const float* __restrict__ bf, float* __restrict__ out, int nN)
{
    __shared__ float Wfs[H * 3];
    const int tid = threadIdx.x;
    for (int i = tid; i < H * 3; i += 256) Wfs[i] = Wf[i];
    __syncthreads();

    const int lane = tid & 31;
    const int node = blockIdx.x * 8 + (tid >> 5);
    if (node >= nN) return;

    const float4 xv = *(const float4*)(x + (size_t)node * H + lane * 4);
    float s0 = 0.f, s1 = 0.f, s2 = 0.f;
    const float xt[4] = {xv.x, xv.y, xv.z, xv.w};
    #pragma unroll
    for (int t = 0; t < 4; t++) {
        const int k = lane * 4 + t;
        s0 = fmaf(xt[t], Wfs[k * 3 + 0], s0);
        s1 = fmaf(xt[t], Wfs[k * 3 + 1], s1);
        s2 = fmaf(xt[t], Wfs[k * 3 + 2], s2);
    }
    #pragma unroll
    for (int off = 16; off > 0; off >>= 1) {
        s0 += __shfl_down_sync(0xFFFFFFFFu, s0, off);
        s1 += __shfl_down_sync(0xFFFFFFFFu, s1, off);
        s2 += __shfl_down_sync(0xFFFFFFFFu, s2, off);
    }
    if (lane == 0) {
        out[(size_t)node * 3 + 0] = s0 + bf[0];
        out[(size_t)node * 3 + 1] = s1 + bf[1];
        out[(size_t)node * 3 + 2] = s2 + bf[2];
    }
}

// ---------------------------------------------------------------------------
extern "C" void kernel_launch(void* const* d_in, const int* in_sizes, int n_in,
                              void* d_out, int out_size)
{
    const float*      x_in = (const float*)d_in[0];
    const int*        ei   = (const int*)d_in[1];
    const float*      W1   = (const float*)d_in[2];
    const float*      b1   = (const float*)d_in[3];
    const float*      W2   = (const float*)d_in[4];
    const float*      b2   = (const float*)d_in[5];
    const float*      Wf   = (const float*)d_in[6];
    const float*      bf   = (const float*)d_in[7];
    float*            out  = (float*)d_out;

    const int nN = in_sizes[0] / H;          // 50000
    const int nE = in_sizes[1] / 2;          // 800000
    const int L  = in_sizes[3] / H;          // 4
    const int nwork = nE + nN;

    void* base = nullptr;
    cudaGetSymbolAddress(&base, g_scratch4);
    float* X1 = (float*)base;
    float* X2 = X1 + NBUF;
    float* A  = X1 + 2 * NBUF;
    float* Bm = X1 + 3 * NBUF;

    void* ibase = nullptr;
    cudaGetSymbolAddress(&ibase, g_iscratch);
    int* cnt  = (int*)ibase;
    int* offs = cnt + 50048;
    int* sSrc = cnt + 2 * 50048;
    int* sDst = sSrc + MAXWORK;

    cudaFuncSetAttribute(edge_mma_kernel, cudaFuncAttributeMaxDynamicSharedMemorySize, EDGE_SMEM);
    cudaFuncSetAttribute(node_mma_kernel, cudaFuncAttributeMaxDynamicSharedMemorySize, NODE_SMEM);

    // ---- sort edges by dst (once; reused by all layers) ----
    cudaMemsetAsync(cnt, 0, 50048 * sizeof(int), 0);
    hist_kernel<<<592, 256>>>(ei, cnt, nE, nN);
    scan_kernel<<<1, 1024>>>(cnt, offs, nN);
    scatter_kernel<<<592, 256>>>(ei, offs, sSrc, sDst, nE, nN);

    const int edgeBlocks = 148 * 2;   // 2 blocks/SM
    float* bufs[2] = {X1, X2};

    const float* cur = x_in;
    for (int l = 0; l < L; l++) {
        node_mma_kernel<<<dim3(74, 2), 256, NODE_SMEM>>>(
            cur, W1 + (size_t)l * 2 * H * H, b1 + (size_t)l * H, A, Bm, nN);
        float* y = bufs[l & 1];
        cudaMemsetAsync(y, 0xFF, (size_t)nN * H * sizeof(float), 0);  // NaN init
        edge_mma_kernel<<<edgeBlocks, 128, EDGE_SMEM>>>(
            A, Bm, W2 + (size_t)l * H * H, b2 + (size_t)l * H, sSrc, sDst, y, nwork);
        cur = y;
    }
    final_kernel<<<(nN + 7) / 8, 256>>>(cur, Wf, bf, out, nN);
}

// round 15
// speedup vs baseline: 1.1180x; 1.0121x over previous
#include <cuda_runtime.h>
#include <cuda_bf16.h>
#include <cstdint>

#define H 128
#define MAXN 50000
#define NBUF ((size_t)MAXN * H)
#define MAXWORK 851968            // >= E + N

#define HP 132    // H-tile pitch (words): %32==4 -> A-frag LDS conflict-free
#define WP 136    // W pitch (words) node kernel: %32==8 -> B-frag conflict-free
#define WPP 264   // paired-W2 pitch: %32==8 -> LDS.64 conflict-free
#define WTILE 16  // edges per warp-tile
#define EDGE_WARPS 4
#define W2P_WORDS (16 * 4 * WPP)                               // 67.6KB
#define EDGE_SMEM ((W2P_WORDS + EDGE_WARPS * WTILE * HP) * 4)  // ~101.4KB -> 2 blocks/SM
#define NODE_SMEM ((2 * 128 * WP + 2 * 64 * HP) * 4)           // ~206.8KB

// float scratch: X1, X2 (ping-pong), A, B (per-node partial GEMMs)
__device__ float4 g_scratch4[4 * NBUF / 4];
// int scratch: cnt[50048] | offs[50048] | sortedSrc[MAXWORK] | sortedDst[MAXWORK]
__device__ int g_iscratch[2 * 50048 + 2 * MAXWORK];

__device__ __forceinline__ void atomicMaxF(float* addr, float v) {
    if (v >= 0.f) atomicMax((int*)addr, __float_as_int(v));
    else          atomicMin((unsigned int*)addr, __float_as_uint(v));
}

__device__ __forceinline__ float tf32r(float x) {
    uint32_t u;
    asm("cvt.rna.tf32.f32 %0, %1;" : "=r"(u) : "f"(x));
    return __uint_as_float(u);
}

__device__ __forceinline__ void prefetchL1(const void* p) {
    asm volatile("prefetch.global.L1 [%0];" :: "l"(p));
}

#define MMA_TF32(acc, a0, a1, a2, a3, b0, b1)                                   \
    asm("mma.sync.aligned.m16n8k8.row.col.f32.tf32.tf32.f32 "                   \
        "{%0,%1,%2,%3}, {%4,%5,%6,%7}, {%8,%9}, {%0,%1,%2,%3};"                 \
        : "+f"(acc[0]), "+f"(acc[1]), "+f"(acc[2]), "+f"(acc[3])                \
        : "r"(a0), "r"(a1), "r"(a2), "r"(a3), "r"(b0), "r"(b1))

// ---------------------------------------------------------------------------
// Sorting (counting sort by dst). Runs once per launch, reused by all layers.
// ---------------------------------------------------------------------------
__global__ void hist_kernel(const int* __restrict__ ei, int* __restrict__ cnt,
                            int nE, int nN)
{
    const int nwork = nE + nN;
    for (int e = blockIdx.x * blockDim.x + threadIdx.x; e < nwork;
         e += gridDim.x * blockDim.x) {
        const int d = (e < nE) ? ei[nE + e] : (e - nE);
        atomicAdd(&cnt[d], 1);
    }
}

__global__ void __launch_bounds__(1024) scan_kernel(
    const int* __restrict__ cnt, int* __restrict__ offs, int nN)
{
    __shared__ int sums[1024];
    const int t = threadIdx.x;
    const int chunk = (nN + 1023) / 1024;
    const int lo = t * chunk;
    const int hi = min(lo + chunk, nN);
    int s = 0;
    for (int i = lo; i < hi; i++) s += cnt[i];
    sums[t] = s;
    __syncthreads();
    for (int off = 1; off < 1024; off <<= 1) {
        int v = (t >= off) ? sums[t - off] : 0;
        __syncthreads();
        sums[t] += v;
        __syncthreads();
    }
    int run = sums[t] - s;   // exclusive prefix
    for (int i = lo; i < hi; i++) {
        offs[i] = run;
        run += cnt[i];
    }
}

__global__ void scatter_kernel(const int* __restrict__ ei, int* __restrict__ offs,
                               int* __restrict__ sSrc, int* __restrict__ sDst,
                               int nE, int nN)
{
    const int nwork = nE + nN;
    for (int e = blockIdx.x * blockDim.x + threadIdx.x; e < nwork;
         e += gridDim.x * blockDim.x) {
        int s, d;
        if (e < nE) { s = ei[e]; d = ei[nE + e]; }
        else        { s = d = e - nE; }
        const int pos = atomicAdd(&offs[d], 1);
        sSrc[pos] = s;
        sDst[pos] = d;
    }
}

// ---------------------------------------------------------------------------
// Node GEMM via tensor cores, 3xTF32 split (fp32-accurate).
// v3: 512 threads (16 warps), warp grid 4(M)x4(N), M=64 tiles, same 2-sync
// structure as R10 -> better latency hiding at constant per-tile MMA volume.
// ---------------------------------------------------------------------------
__global__ void __launch_bounds__(512) node_mma_kernel(
    const float* __restrict__ x, const float* __restrict__ W1l,
    const float* __restrict__ b1l, float* __restrict__ A, float* __restrict__ Bm,
    int nN)
{
    extern __shared__ float sm[];
    float* Wh = sm;                  // [128][WP]
    float* Wl = sm + 128 * WP;       // [128][WP]
    float* Xh = sm + 2 * 128 * WP;   // [64][HP]
    float* Xl = Xh + 64 * HP;        // [64][HP]

    const int tid  = threadIdx.x;
    const int lane = tid & 31;
    const int wid  = tid >> 5;
    const int mg   = wid >> 2;      // 0..3 : rows 16*mg..16*mg+15
    const int ng   = wid & 3;       // 0..3 : cols 32*ng..
    const int lr   = lane >> 2;     // 0..7
    const int lc   = lane & 3;      // 0..3
    const int half = blockIdx.y;

    for (int i = tid; i < 128 * 128; i += 512) {
        const int k = i >> 7, j = i & 127;
        float wv = (half == 0)
            ? (W1l[k * H + j] - W1l[(H + k) * H + j])
            : W1l[(H + k) * H + j];
        const float hi = tf32r(wv);
        Wh[k * WP + j] = hi;
        Wl[k * WP + j] = tf32r(wv - hi);
    }

    float2 b1c[4];
    #pragma unroll
    for (int ni = 0; ni < 4; ni++) {
        if (half == 0) b1c[ni] = *(const float2*)(b1l + 32 * ng + 8 * ni + 2 * lc);
        else           b1c[ni] = make_float2(0.f, 0.f);
    }
    float* outP = (half == 0) ? A : Bm;
    __syncthreads();

    const int ntiles = (nN + 63) / 64;
    for (int tile = blockIdx.x; tile < ntiles; tile += gridDim.x) {
        const int n0 = tile * 64;

        for (int i = tid; i < 64 * 32; i += 512) {
            const int r = i >> 5, j4 = (i & 31) * 4;
            float4 v = (n0 + r < nN)
                ? *(const float4*)(x + (size_t)(n0 + r) * H + j4)
                : make_float4(0.f, 0.f, 0.f, 0.f);
            float4 hi4, lo4;
            hi4.x = tf32r(v.x); lo4.x = tf32r(v.x - hi4.x);
            hi4.y = tf32r(v.y); lo4.y = tf32r(v.y - hi4.y);
            hi4.z = tf32r(v.z); lo4.z = tf32r(v.z - hi4.z);
            hi4.w = tf32r(v.w); lo4.w = tf32r(v.w - hi4.w);
            *(float4*)(Xh + r * HP + j4) = hi4;
            *(float4*)(Xl + r * HP + j4) = lo4;
        }
        __syncthreads();

        float acc[4][4];
        #pragma unroll
        for (int ni = 0; ni < 4; ni++)
            #pragma unroll
            for (int c = 0; c < 4; c++) acc[ni][c] = 0.f;

        #pragma unroll
        for (int ks = 0; ks < 16; ks++) {
            const int kb = ks * 8;
            const int ro = (16 * mg + lr) * HP + kb + lc;
            const uint32_t ah0 = __float_as_uint(Xh[ro]);
            const uint32_t ah1 = __float_as_uint(Xh[ro + 8 * HP]);
            const uint32_t ah2 = __float_as_uint(Xh[ro + 4]);
            const uint32_t ah3 = __float_as_uint(Xh[ro + 8 * HP + 4]);
            const uint32_t al0 = __float_as_uint(Xl[ro]);
            const uint32_t al1 = __float_as_uint(Xl[ro + 8 * HP]);
            const uint32_t al2 = __float_as_uint(Xl[ro + 4]);
            const uint32_t al3 = __float_as_uint(Xl[ro + 8 * HP + 4]);
            #pragma unroll
            for (int ni = 0; ni < 4; ni++) {
                const int bo = (kb + lc) * WP + 32 * ng + 8 * ni + lr;
                const uint32_t bh0 = __float_as_uint(Wh[bo]);
                const uint32_t bh1 = __float_as_uint(Wh[bo + 4 * WP]);
                const uint32_t bl0 = __float_as_uint(Wl[bo]);
                const uint32_t bl1 = __float_as_uint(Wl[bo + 4 * WP]);
                MMA_TF32(acc[ni], ah0, ah1, ah2, ah3, bh0, bh1);
                MMA_TF32(acc[ni], al0, al1, al2, al3, bh0, bh1);
                MMA_TF32(acc[ni], ah0, ah1, ah2, ah3, bl0, bl1);
            }
        }
        __syncthreads();

        {
            const int r0 = 16 * mg + lr;
            #pragma unroll
            for (int ni = 0; ni < 4; ni++) {
                const int col = 32 * ng + 8 * ni + 2 * lc;
                if (n0 + r0 < nN)
                    *(float2*)(outP + (size_t)(n0 + r0) * H + col) =
                        make_float2(acc[ni][0] + b1c[ni].x, acc[ni][1] + b1c[ni].y);
                if (n0 + r0 + 8 < nN)
                    *(float2*)(outP + (size_t)(n0 + r0 + 8) * H + col) =
                        make_float2(acc[ni][2] + b1c[ni].x, acc[ni][3] + b1c[ni].y);
            }
        }
    }
}

// ---------------------------------------------------------------------------
// Edge kernel (R10 + paired-k W2 + next-tile index/row prefetch):
// warp-independent 16-edge tiles, 4 warps/block, 2 blocks/SM.
// No __syncthreads in loop.
// ---------------------------------------------------------------------------
__global__ void __launch_bounds__(128, 2) edge_mma_kernel(
    const float* __restrict__ A, const float* __restrict__ Bm,
    const float* __restrict__ W2, const float* __restrict__ b2,
    const int* __restrict__ sSrc, const int* __restrict__ sDst,
    float* __restrict__ y, int nwork)
{
    extern __shared__ float sm[];
    float* W2p = sm;                               // [64][WPP]: (ks,lc) -> 128 float2
    const int tid  = threadIdx.x;
    const int lane = tid & 31;
    const int wid  = tid >> 5;
    float* Hs = sm + W2P_WORDS + wid * (WTILE * HP); // per-warp [16][HP]

    // W2 -> paired layout: W2p[(ks*4+lc)*WPP + 2*col] = (tf32 W2[8ks+lc][col], tf32 W2[8ks+lc+4][col])
    for (int i = tid; i < 64 * 128; i += 128) {
        const int pr  = i >> 7;        // 0..63
        const int col = i & 127;
        const int k   = (pr >> 2) * 8 + (pr & 3);
        const float v0 = tf32r(W2[k * H + col]);
        const float v1 = tf32r(W2[(k + 4) * H + col]);
        *(float2*)(W2p + pr * WPP + 2 * col) = make_float2(v0, v1);
    }
    const float4 b2c = *(const float4*)(b2 + lane * 4);
    __syncthreads();   // only barrier: W2p ready

    const int lr   = lane >> 2;     // 0..7
    const int lc   = lane & 3;      // 0..3
    const int eL   = lane >> 1;     // 0..15 : my build row
    const int half = lane & 1;      // 0..1  : column half

    const int ntiles = (nwork + WTILE - 1) / WTILE;
    const int gw     = blockIdx.x * EDGE_WARPS + wid;
    const int stride = gridDim.x * EDGE_WARPS;

    // preload first tile's indices
    int tile = gw;
    int s = -1, d = -1;
    if (tile < ntiles) {
        const int e = tile * WTILE + eL;
        if (e < nwork) { s = sSrc[e]; d = sDst[e]; }
    }

    while (tile < ntiles) {
        const int nextTile = tile + stride;

        // kick next tile's index loads early (needed ~2000 cyc from now)
        int sN = -1, dN = -1;
        if (nextTile < ntiles) {
            const int e = nextTile * WTILE + eL;
            if (e < nwork) { sN = sSrc[e]; dN = sDst[e]; }
        }

        // ---- build: lane = (row eL, half) -> 64 cols ----
        {
            float* hrow = Hs + eL * HP + half * 64;
            if (d >= 0) {
                const float4* ap = (const float4*)(A  + (size_t)d * H + half * 64);
                const float4* bp = (const float4*)(Bm + (size_t)s * H + half * 64);
                #pragma unroll
                for (int i = 0; i < 16; i++) {
                    const float4 a = ap[i], b = bp[i];
                    float4 hh;
                    hh.x = tf32r(fmaxf(a.x + b.x, 0.f));
                    hh.y = tf32r(fmaxf(a.y + b.y, 0.f));
                    hh.z = tf32r(fmaxf(a.z + b.z, 0.f));
                    hh.w = tf32r(fmaxf(a.w + b.w, 0.f));
                    *(float4*)(hrow + i * 4) = hh;
                }
            } else {
                #pragma unroll
                for (int i = 0; i < 16; i++)
                    *(float4*)(hrow + i * 4) = make_float4(0.f, 0.f, 0.f, 0.f);
            }
        }
        __syncwarp();

        // ---- mma: m16 x n128 x k128, B via LDS.64 paired loads ----
        float acc[16][4];
        #pragma unroll
        for (int ni = 0; ni < 16; ni++)
            #pragma unroll
            for (int c = 0; c < 4; c++) acc[ni][c] = 0.f;

        #pragma unroll
        for (int ks = 0; ks < 16; ks++) {
            const int kb = ks * 8;
            const float* ab = Hs + lr * HP + kb + lc;
            const uint32_t a0 = __float_as_uint(ab[0]);
            const uint32_t a1 = __float_as_uint(ab[8 * HP]);
            const uint32_t a2 = __float_as_uint(ab[4]);
            const uint32_t a3 = __float_as_uint(ab[8 * HP + 4]);
            const float* bbase = W2p + (ks * 4 + lc) * WPP + 2 * lr;
            #pragma unroll
            for (int ni = 0; ni < 16; ni++) {
                const float2 bp = *(const float2*)(bbase + 16 * ni);
                MMA_TF32(acc[ni], a0, a1, a2, a3,
                         __float_as_uint(bp.x), __float_as_uint(bp.y));
            }
        }
        __syncwarp();   // frag reads done before writeback overwrites Hs

        // ---- writeback raw acc into Hs ----
        #pragma unroll
        for (int ni = 0; ni < 16; ni++) {
            const int col = 8 * ni + 2 * lc;
            *(float2*)(Hs + lr * HP + col)       = make_float2(acc[ni][0], acc[ni][1]);
            *(float2*)(Hs + (lr + 8) * HP + col) = make_float2(acc[ni][2], acc[ni][3]);
        }

        // ---- prefetch next tile's gather rows into L1 (covers reduce latency) ----
        if (dN >= 0) {
            const char* ap = (const char*)(A  + (size_t)dN * H + half * 64);
            const char* bp = (const char*)(Bm + (size_t)sN * H + half * 64);
            prefetchL1(ap); prefetchL1(ap + 128);
            prefetchL1(bp); prefetchL1(bp + 128);
        }
        __syncwarp();

        // ---- segmented max over 16 sorted rows; lane = 4 cols; b2 folded ----
        {
            int cur_d = -1;
            float4 m = make_float4(0.f, 0.f, 0.f, 0.f);
            #pragma unroll
            for (int r = 0; r < 16; r++) {
                const int dr = __shfl_sync(0xFFFFFFFFu, d, 2 * r);
                const float4 v = *(const float4*)(Hs + r * HP + lane * 4);
                if (dr != cur_d) {
                    if (cur_d >= 0) {
                        float* yr = y + (size_t)cur_d * H + lane * 4;
                        atomicMaxF(yr + 0, m.x + b2c.x);
                        atomicMaxF(yr + 1, m.y + b2c.y);
                        atomicMaxF(yr + 2, m.z + b2c.z);
                        atomicMaxF(yr + 3, m.w + b2c.w);
                    }
                    cur_d = dr;
                    m = v;
                } else {
                    m.x = fmaxf(m.x, v.x); m.y = fmaxf(m.y, v.y);
                    m.z = fmaxf(m.z, v.z); m.w = fmaxf(m.w, v.w);
                }
            }
            if (cur_d >= 0) {
                float* yr = y + (size_t)cur_d * H + lane * 4;
                atomicMaxF(yr + 0, m.x + b2c.x);
                atomicMaxF(yr + 1, m.y + b2c.y);
                atomicMaxF(yr + 2, m.z + b2c.z);
                atomicMaxF(yr + 3, m.w + b2c.w);
            }
        }
        __syncwarp();   // reduce reads done before next build overwrites Hs

        s = sN; d = dN; tile = nextTile;
    }
}

// ---------------------------------------------------------------------------
// Final: out[n] = x[n] @ Wf + bf   (H=128 -> D=3). Warp per node.
// ---------------------------------------------------------------------------
__global__ void __launch_bounds__(256) final_kernel(
    const float* __restrict__ x, const float* __restrict__ Wf,
    const float* __restrict__ bf, float* __restrict__ out, int nN)
{
    __shared__ float Wfs[H * 3];
    const int tid = threadIdx.x;
    for (int i = tid; i < H * 3; i += 256) Wfs[i] = Wf[i];
    __syncthreads();

    const int lane = tid & 31;
    const int node = blockIdx.x * 8 + (tid >> 5);
    if (node >= nN) return;

    const float4 xv = *(const float4*)(x + (size_t)node * H + lane * 4);
    float s0 = 0.f, s1 = 0.f, s2 = 0.f;
    const float xt[4] = {xv.x, xv.y, xv.z, xv.w};
    #pragma unroll
    for (int t = 0; t < 4; t++) {
        const int k = lane * 4 + t;
        s0 = fmaf(xt[t], Wfs[k * 3 + 0], s0);
        s1 = fmaf(xt[t], Wfs[k * 3 + 1], s1);
        s2 = fmaf(xt[t], Wfs[k * 3 + 2], s2);
    }
    #pragma unroll
    for (int off = 16; off > 0; off >>= 1) {
        s0 += __shfl_down_sync(0xFFFFFFFFu, s0, off);
        s1 += __shfl_down_sync(0xFFFFFFFFu, s1, off);
        s2 += __shfl_down_sync(0xFFFFFFFFu, s2, off);
    }
    if (lane == 0) {
        out[(size_t)node * 3 + 0] = s0 + bf[0];
        out[(size_t)node * 3 + 1] = s1 + bf[1];
        out[(size_t)node * 3 + 2] = s2 + bf[2];
    }
}

// ---------------------------------------------------------------------------
extern "C" void kernel_launch(void* const* d_in, const int* in_sizes, int n_in,
                              void* d_out, int out_size)
{
    const float*      x_in = (const float*)d_in[0];
    const int*        ei   = (const int*)d_in[1];
    const float*      W1   = (const float*)d_in[2];
    const float*      b1   = (const float*)d_in[3];
    const float*      W2   = (const float*)d_in[4];
    const float*      b2   = (const float*)d_in[5];
    const float*      Wf   = (const float*)d_in[6];
    const float*      bf   = (const float*)d_in[7];
    float*            out  = (float*)d_out;

    const int nN = in_sizes[0] / H;          // 50000
    const int nE = in_sizes[1] / 2;          // 800000
    const int L  = in_sizes[3] / H;          // 4
    const int nwork = nE + nN;

    void* base = nullptr;
    cudaGetSymbolAddress(&base, g_scratch4);
    float* X1 = (float*)base;
    float* X2 = X1 + NBUF;
    float* A  = X1 + 2 * NBUF;
    float* Bm = X1 + 3 * NBUF;

    void* ibase = nullptr;
    cudaGetSymbolAddress(&ibase, g_iscratch);
    int* cnt  = (int*)ibase;
    int* offs = cnt + 50048;
    int* sSrc = cnt + 2 * 50048;
    int* sDst = sSrc + MAXWORK;

    cudaFuncSetAttribute(edge_mma_kernel, cudaFuncAttributeMaxDynamicSharedMemorySize, EDGE_SMEM);
    cudaFuncSetAttribute(node_mma_kernel, cudaFuncAttributeMaxDynamicSharedMemorySize, NODE_SMEM);

    // ---- sort edges by dst (once; reused by all layers) ----
    cudaMemsetAsync(cnt, 0, 50048 * sizeof(int), 0);
    hist_kernel<<<592, 256>>>(ei, cnt, nE, nN);
    scan_kernel<<<1, 1024>>>(cnt, offs, nN);
    scatter_kernel<<<592, 256>>>(ei, offs, sSrc, sDst, nE, nN);

    const int edgeBlocks = 148 * 2;   // 2 blocks/SM
    float* bufs[2] = {X1, X2};

    const float* cur = x_in;
    for (int l = 0; l < L; l++) {
        node_mma_kernel<<<dim3(74, 2), 512, NODE_SMEM>>>(
            cur, W1 + (size_t)l * 2 * H * H, b1 + (size_t)l * H, A, Bm, nN);
        float* y = bufs[l & 1];
        cudaMemsetAsync(y, 0xFF, (size_t)nN * H * sizeof(float), 0);  // NaN init
        edge_mma_kernel<<<edgeBlocks, 128, EDGE_SMEM>>>(
            A, Bm, W2 + (size_t)l * H * H, b2 + (size_t)l * H, sSrc, sDst, y, nwork);
        cur = y;
    }
    final_kernel<<<(nN + 7) / 8, 256>>>(cur, Wf, bf, out, nN);
}

// round 16
// speedup vs baseline: 1.1269x; 1.0080x over previous
#include <cuda_runtime.h>
#include <cuda_bf16.h>
#include <cstdint>

#define H 128
#define MAXN 50000
#define NBUF ((size_t)MAXN * H)
#define MAXWORK 851968            // >= E + N

#define HP 132    // H-tile pitch (words): %32==4 -> A-frag LDS conflict-free
#define WP 136    // W pitch (words) node kernel: %32==8 -> B-frag conflict-free
#define WPP 264   // paired-W2 pitch: %32==8 -> LDS.64 conflict-free
#define WTILE 16  // edges per warp-tile
#define EDGE_WARPS 4
#define W2P_WORDS (16 * 4 * WPP)                               // 67.6KB
#define EDGE_SMEM ((W2P_WORDS + EDGE_WARPS * WTILE * HP) * 4)  // ~101.4KB -> 2 blocks/SM
#define NODE_SMEM ((2 * 128 * WP + 2 * 64 * HP) * 4)           // ~206.8KB

// float scratch: X1, X2 (ping-pong), A, B (per-node partial GEMMs)
__device__ float4 g_scratch4[4 * NBUF / 4];
// int scratch: cnt[50048] | offs[50048] | sortedSrc[MAXWORK] | sortedDst[MAXWORK]
__device__ int g_iscratch[2 * 50048 + 2 * MAXWORK];

__device__ __forceinline__ void atomicMaxF(float* addr, float v) {
    if (v >= 0.f) atomicMax((int*)addr, __float_as_int(v));
    else          atomicMin((unsigned int*)addr, __float_as_uint(v));
}

__device__ __forceinline__ float tf32r(float x) {
    uint32_t u;
    asm("cvt.rna.tf32.f32 %0, %1;" : "=r"(u) : "f"(x));
    return __uint_as_float(u);
}

__device__ __forceinline__ void prefetchL1(const void* p) {
    asm volatile("prefetch.global.L1 [%0];" :: "l"(p));
}

#define MMA_TF32(acc, a0, a1, a2, a3, b0, b1)                                   \
    asm("mma.sync.aligned.m16n8k8.row.col.f32.tf32.tf32.f32 "                   \
        "{%0,%1,%2,%3}, {%4,%5,%6,%7}, {%8,%9}, {%0,%1,%2,%3};"                 \
        : "+f"(acc[0]), "+f"(acc[1]), "+f"(acc[2]), "+f"(acc[3])                \
        : "r"(a0), "r"(a1), "r"(a2), "r"(a3), "r"(b0), "r"(b1))

// ---------------------------------------------------------------------------
// Sorting (counting sort by dst). Runs once per launch, reused by all layers.
// ---------------------------------------------------------------------------
__global__ void hist_kernel(const int* __restrict__ ei, int* __restrict__ cnt,
                            int nE, int nN)
{
    const int nwork = nE + nN;
    for (int e = blockIdx.x * blockDim.x + threadIdx.x; e < nwork;
         e += gridDim.x * blockDim.x) {
        const int d = (e < nE) ? ei[nE + e] : (e - nE);
        atomicAdd(&cnt[d], 1);
    }
}

__global__ void __launch_bounds__(1024) scan_kernel(
    const int* __restrict__ cnt, int* __restrict__ offs, int nN)
{
    __shared__ int sums[1024];
    const int t = threadIdx.x;
    const int chunk = (nN + 1023) / 1024;
    const int lo = t * chunk;
    const int hi = min(lo + chunk, nN);
    int s = 0;
    for (int i = lo; i < hi; i++) s += cnt[i];
    sums[t] = s;
    __syncthreads();
    for (int off = 1; off < 1024; off <<= 1) {
        int v = (t >= off) ? sums[t - off] : 0;
        __syncthreads();
        sums[t] += v;
        __syncthreads();
    }
    int run = sums[t] - s;   // exclusive prefix
    for (int i = lo; i < hi; i++) {
        offs[i] = run;
        run += cnt[i];
    }
}

__global__ void scatter_kernel(const int* __restrict__ ei, int* __restrict__ offs,
                               int* __restrict__ sSrc, int* __restrict__ sDst,
                               int nE, int nN)
{
    const int nwork = nE + nN;
    for (int e = blockIdx.x * blockDim.x + threadIdx.x; e < nwork;
         e += gridDim.x * blockDim.x) {
        int s, d;
        if (e < nE) { s = ei[e]; d = ei[nE + e]; }
        else        { s = d = e - nE; }
        const int pos = atomicAdd(&offs[d], 1);
        sSrc[pos] = s;
        sDst[pos] = d;
    }
}

// ---------------------------------------------------------------------------
// Node GEMM via tensor cores, 3xTF32 split (fp32-accurate). R10 proven shape:
// 256 threads (8 warps), warp grid 2(M)x4(N), M=64 tiles, 2 syncs per tile.
// ---------------------------------------------------------------------------
__global__ void __launch_bounds__(256) node_mma_kernel(
    const float* __restrict__ x, const float* __restrict__ W1l,
    const float* __restrict__ b1l, float* __restrict__ A, float* __restrict__ Bm,
    int nN)
{
    extern __shared__ float sm[];
    float* Wh = sm;                  // [128][WP]
    float* Wl = sm + 128 * WP;       // [128][WP]
    float* Xh = sm + 2 * 128 * WP;   // [64][HP]
    float* Xl = Xh + 64 * HP;        // [64][HP]

    const int tid  = threadIdx.x;
    const int lane = tid & 31;
    const int wid  = tid >> 5;
    const int mg   = wid >> 2;      // 0..1
    const int ng   = wid & 3;       // 0..3
    const int lr   = lane >> 2;     // 0..7
    const int lc   = lane & 3;      // 0..3
    const int half = blockIdx.y;

    for (int i = tid; i < 128 * 128; i += 256) {
        const int k = i >> 7, j = i & 127;
        float wv = (half == 0)
            ? (W1l[k * H + j] - W1l[(H + k) * H + j])
            : W1l[(H + k) * H + j];
        const float hi = tf32r(wv);
        Wh[k * WP + j] = hi;
        Wl[k * WP + j] = tf32r(wv - hi);
    }

    float2 b1c[4];
    #pragma unroll
    for (int ni = 0; ni < 4; ni++) {
        if (half == 0) b1c[ni] = *(const float2*)(b1l + 32 * ng + 8 * ni + 2 * lc);
        else           b1c[ni] = make_float2(0.f, 0.f);
    }
    float* outP = (half == 0) ? A : Bm;
    __syncthreads();

    const int ntiles = (nN + 63) / 64;
    for (int tile = blockIdx.x; tile < ntiles; tile += gridDim.x) {
        const int n0 = tile * 64;

        for (int i = tid; i < 64 * 32; i += 256) {
            const int r = i >> 5, j4 = (i & 31) * 4;
            float4 v = (n0 + r < nN)
                ? *(const float4*)(x + (size_t)(n0 + r) * H + j4)
                : make_float4(0.f, 0.f, 0.f, 0.f);
            float4 hi4, lo4;
            hi4.x = tf32r(v.x); lo4.x = tf32r(v.x - hi4.x);
            hi4.y = tf32r(v.y); lo4.y = tf32r(v.y - hi4.y);
            hi4.z = tf32r(v.z); lo4.z = tf32r(v.z - hi4.z);
            hi4.w = tf32r(v.w); lo4.w = tf32r(v.w - hi4.w);
            *(float4*)(Xh + r * HP + j4) = hi4;
            *(float4*)(Xl + r * HP + j4) = lo4;
        }
        __syncthreads();

        float acc[2][4][4];
        #pragma unroll
        for (int mi = 0; mi < 2; mi++)
            #pragma unroll
            for (int ni = 0; ni < 4; ni++)
                #pragma unroll
                for (int c = 0; c < 4; c++) acc[mi][ni][c] = 0.f;

        #pragma unroll
        for (int ks = 0; ks < 16; ks++) {
            const int kb = ks * 8;
            uint32_t ah[2][4], al[2][4];
            #pragma unroll
            for (int mi = 0; mi < 2; mi++) {
                const int ro = (32 * mg + 16 * mi + lr) * HP + kb + lc;
                ah[mi][0] = __float_as_uint(Xh[ro]);
                ah[mi][1] = __float_as_uint(Xh[ro + 8 * HP]);
                ah[mi][2] = __float_as_uint(Xh[ro + 4]);
                ah[mi][3] = __float_as_uint(Xh[ro + 8 * HP + 4]);
                al[mi][0] = __float_as_uint(Xl[ro]);
                al[mi][1] = __float_as_uint(Xl[ro + 8 * HP]);
                al[mi][2] = __float_as_uint(Xl[ro + 4]);
                al[mi][3] = __float_as_uint(Xl[ro + 8 * HP + 4]);
            }
            #pragma unroll
            for (int ni = 0; ni < 4; ni++) {
                const int bo = (kb + lc) * WP + 32 * ng + 8 * ni + lr;
                const uint32_t bh0 = __float_as_uint(Wh[bo]);
                const uint32_t bh1 = __float_as_uint(Wh[bo + 4 * WP]);
                const uint32_t bl0 = __float_as_uint(Wl[bo]);
                const uint32_t bl1 = __float_as_uint(Wl[bo + 4 * WP]);
                #pragma unroll
                for (int mi = 0; mi < 2; mi++) {
                    MMA_TF32(acc[mi][ni], ah[mi][0], ah[mi][1], ah[mi][2], ah[mi][3], bh0, bh1);
                    MMA_TF32(acc[mi][ni], al[mi][0], al[mi][1], al[mi][2], al[mi][3], bh0, bh1);
                    MMA_TF32(acc[mi][ni], ah[mi][0], ah[mi][1], ah[mi][2], ah[mi][3], bl0, bl1);
                }
            }
        }
        __syncthreads();

        #pragma unroll
        for (int mi = 0; mi < 2; mi++) {
            const int r0 = 32 * mg + 16 * mi + lr;
            #pragma unroll
            for (int ni = 0; ni < 4; ni++) {
                const int col = 32 * ng + 8 * ni + 2 * lc;
                if (n0 + r0 < nN)
                    *(float2*)(outP + (size_t)(n0 + r0) * H + col) =
                        make_float2(acc[mi][ni][0] + b1c[ni].x, acc[mi][ni][1] + b1c[ni].y);
                if (n0 + r0 + 8 < nN)
                    *(float2*)(outP + (size_t)(n0 + r0 + 8) * H + col) =
                        make_float2(acc[mi][ni][2] + b1c[ni].x, acc[mi][ni][3] + b1c[ni].y);
            }
        }
    }
}

// ---------------------------------------------------------------------------
// Edge kernel (R10 + paired-k W2 + next-tile index/row prefetch):
// warp-independent 16-edge tiles, 4 warps/block, 2 blocks/SM.
// No __syncthreads in loop.
// ---------------------------------------------------------------------------
__global__ void __launch_bounds__(128, 2) edge_mma_kernel(
    const float* __restrict__ A, const float* __restrict__ Bm,
    const float* __restrict__ W2, const float* __restrict__ b2,
    const int* __restrict__ sSrc, const int* __restrict__ sDst,
    float* __restrict__ y, int nwork)
{
    extern __shared__ float sm[];
    float* W2p = sm;                               // [64][WPP]: (ks,lc) -> 128 float2
    const int tid  = threadIdx.x;
    const int lane = tid & 31;
    const int wid  = tid >> 5;
    float* Hs = sm + W2P_WORDS + wid * (WTILE * HP); // per-warp [16][HP]

    // W2 -> paired layout: W2p[(ks*4+lc)*WPP + 2*col] = (tf32 W2[8ks+lc][col], tf32 W2[8ks+lc+4][col])
    for (int i = tid; i < 64 * 128; i += 128) {
        const int pr  = i >> 7;        // 0..63
        const int col = i & 127;
        const int k   = (pr >> 2) * 8 + (pr & 3);
        const float v0 = tf32r(W2[k * H + col]);
        const float v1 = tf32r(W2[(k + 4) * H + col]);
        *(float2*)(W2p + pr * WPP + 2 * col) = make_float2(v0, v1);
    }
    const float4 b2c = *(const float4*)(b2 + lane * 4);
    __syncthreads();   // only barrier: W2p ready

    const int lr   = lane >> 2;     // 0..7
    const int lc   = lane & 3;      // 0..3
    const int eL   = lane >> 1;     // 0..15 : my build row
    const int half = lane & 1;      // 0..1  : column half

    const int ntiles = (nwork + WTILE - 1) / WTILE;
    const int gw     = blockIdx.x * EDGE_WARPS + wid;
    const int stride = gridDim.x * EDGE_WARPS;

    // preload first tile's indices
    int tile = gw;
    int s = -1, d = -1;
    if (tile < ntiles) {
        const int e = tile * WTILE + eL;
        if (e < nwork) { s = sSrc[e]; d = sDst[e]; }
    }

    while (tile < ntiles) {
        const int nextTile = tile + stride;

        // kick next tile's index loads early (needed ~2000 cyc from now)
        int sN = -1, dN = -1;
        if (nextTile < ntiles) {
            const int e = nextTile * WTILE + eL;
            if (e < nwork) { sN = sSrc[e]; dN = sDst[e]; }
        }

        // ---- build: lane = (row eL, half) -> 64 cols ----
        {
            float* hrow = Hs + eL * HP + half * 64;
            if (d >= 0) {
                const float4* ap = (const float4*)(A  + (size_t)d * H + half * 64);
                const float4* bp = (const float4*)(Bm + (size_t)s * H + half * 64);
                #pragma unroll
                for (int i = 0; i < 16; i++) {
                    const float4 a = ap[i], b = bp[i];
                    float4 hh;
                    hh.x = tf32r(fmaxf(a.x + b.x, 0.f));
                    hh.y = tf32r(fmaxf(a.y + b.y, 0.f));
                    hh.z = tf32r(fmaxf(a.z + b.z, 0.f));
                    hh.w = tf32r(fmaxf(a.w + b.w, 0.f));
                    *(float4*)(hrow + i * 4) = hh;
                }
            } else {
                #pragma unroll
                for (int i = 0; i < 16; i++)
                    *(float4*)(hrow + i * 4) = make_float4(0.f, 0.f, 0.f, 0.f);
            }
        }
        __syncwarp();

        // ---- mma: m16 x n128 x k128, B via LDS.64 paired loads ----
        float acc[16][4];
        #pragma unroll
        for (int ni = 0; ni < 16; ni++)
            #pragma unroll
            for (int c = 0; c < 4; c++) acc[ni][c] = 0.f;

        #pragma unroll
        for (int ks = 0; ks < 16; ks++) {
            const int kb = ks * 8;
            const float* ab = Hs + lr * HP + kb + lc;
            const uint32_t a0 = __float_as_uint(ab[0]);
            const uint32_t a1 = __float_as_uint(ab[8 * HP]);
            const uint32_t a2 = __float_as_uint(ab[4]);
            const uint32_t a3 = __float_as_uint(ab[8 * HP + 4]);
            const float* bbase = W2p + (ks * 4 + lc) * WPP + 2 * lr;
            #pragma unroll
            for (int ni = 0; ni < 16; ni++) {
                const float2 bp = *(const float2*)(bbase + 16 * ni);
                MMA_TF32(acc[ni], a0, a1, a2, a3,
                         __float_as_uint(bp.x), __float_as_uint(bp.y));
            }
        }
        __syncwarp();   // frag reads done before writeback overwrites Hs

        // ---- writeback raw acc into Hs ----
        #pragma unroll
        for (int ni = 0; ni < 16; ni++) {
            const int col = 8 * ni + 2 * lc;
            *(float2*)(Hs + lr * HP + col)       = make_float2(acc[ni][0], acc[ni][1]);
            *(float2*)(Hs + (lr + 8) * HP + col) = make_float2(acc[ni][2], acc[ni][3]);
        }

        // ---- prefetch next tile's gather rows into L1 (covers reduce latency) ----
        if (dN >= 0) {
            const char* ap = (const char*)(A  + (size_t)dN * H + half * 64);
            const char* bp = (const char*)(Bm + (size_t)sN * H + half * 64);
            prefetchL1(ap); prefetchL1(ap + 128);
            prefetchL1(bp); prefetchL1(bp + 128);
        }
        __syncwarp();

        // ---- segmented max over 16 sorted rows; lane = 4 cols; b2 folded ----
        {
            int cur_d = -1;
            float4 m = make_float4(0.f, 0.f, 0.f, 0.f);
            #pragma unroll
            for (int r = 0; r < 16; r++) {
                const int dr = __shfl_sync(0xFFFFFFFFu, d, 2 * r);
                const float4 v = *(const float4*)(Hs + r * HP + lane * 4);
                if (dr != cur_d) {
                    if (cur_d >= 0) {
                        float* yr = y + (size_t)cur_d * H + lane * 4;
                        atomicMaxF(yr + 0, m.x + b2c.x);
                        atomicMaxF(yr + 1, m.y + b2c.y);
                        atomicMaxF(yr + 2, m.z + b2c.z);
                        atomicMaxF(yr + 3, m.w + b2c.w);
                    }
                    cur_d = dr;
                    m = v;
                } else {
                    m.x = fmaxf(m.x, v.x); m.y = fmaxf(m.y, v.y);
                    m.z = fmaxf(m.z, v.z); m.w = fmaxf(m.w, v.w);
                }
            }
            if (cur_d >= 0) {
                float* yr = y + (size_t)cur_d * H + lane * 4;
                atomicMaxF(yr + 0, m.x + b2c.x);
                atomicMaxF(yr + 1, m.y + b2c.y);
                atomicMaxF(yr + 2, m.z + b2c.z);
                atomicMaxF(yr + 3, m.w + b2c.w);
            }
        }
        __syncwarp();   // reduce reads done before next build overwrites Hs

        s = sN; d = dN; tile = nextTile;
    }
}

// ---------------------------------------------------------------------------
// Final: out[n] = x[n] @ Wf + bf   (H=128 -> D=3). Warp per node.
// ---------------------------------------------------------------------------
__global__ void __launch_bounds__(256) final_kernel(
    const float* __restrict__ x, const float* __restrict__ Wf,
    const float* __restrict__ bf, float* __restrict__ out, int nN)
{
    __shared__ float Wfs[H * 3];
    const int tid = threadIdx.x;
    for (int i = tid; i < H * 3; i += 256) Wfs[i] = Wf[i];
    __syncthreads();

    const int lane = tid & 31;
    const int node = blockIdx.x * 8 + (tid >> 5);
    if (node >= nN) return;

    const float4 xv = *(const float4*)(x + (size_t)node * H + lane * 4);
    float s0 = 0.f, s1 = 0.f, s2 = 0.f;
    const float xt[4] = {xv.x, xv.y, xv.z, xv.w};
    #pragma unroll
    for (int t = 0; t < 4; t++) {
        const int k = lane * 4 + t;
        s0 = fmaf(xt[t], Wfs[k * 3 + 0], s0);
        s1 = fmaf(xt[t], Wfs[k * 3 + 1], s1);
        s2 = fmaf(xt[t], Wfs[k * 3 + 2], s2);
    }
    #pragma unroll
    for (int off = 16; off > 0; off >>= 1) {
        s0 += __shfl_down_sync(0xFFFFFFFFu, s0, off);
        s1 += __shfl_down_sync(0xFFFFFFFFu, s1, off);
        s2 += __shfl_down_sync(0xFFFFFFFFu, s2, off);
    }
    if (lane == 0) {
        out[(size_t)node * 3 + 0] = s0 + bf[0];
        out[(size_t)node * 3 + 1] = s1 + bf[1];
        out[(size_t)node * 3 + 2] = s2 + bf[2];
    }
}

// ---------------------------------------------------------------------------
extern "C" void kernel_launch(void* const* d_in, const int* in_sizes, int n_in,
                              void* d_out, int out_size)
{
    const float*      x_in = (const float*)d_in[0];
    const int*        ei   = (const int*)d_in[1];
    const float*      W1   = (const float*)d_in[2];
    const float*      b1   = (const float*)d_in[3];
    const float*      W2   = (const float*)d_in[4];
    const float*      b2   = (const float*)d_in[5];
    const float*      Wf   = (const float*)d_in[6];
    const float*      bf   = (const float*)d_in[7];
    float*            out  = (float*)d_out;

    const int nN = in_sizes[0] / H;          // 50000
    const int nE = in_sizes[1] / 2;          // 800000
    const int L  = in_sizes[3] / H;          // 4
    const int nwork = nE + nN;

    void* base = nullptr;
    cudaGetSymbolAddress(&base, g_scratch4);
    float* X1 = (float*)base;
    float* X2 = X1 + NBUF;
    float* A  = X1 + 2 * NBUF;
    float* Bm = X1 + 3 * NBUF;

    void* ibase = nullptr;
    cudaGetSymbolAddress(&ibase, g_iscratch);
    int* cnt  = (int*)ibase;
    int* offs = cnt + 50048;
    int* sSrc = cnt + 2 * 50048;
    int* sDst = sSrc + MAXWORK;

    cudaFuncSetAttribute(edge_mma_kernel, cudaFuncAttributeMaxDynamicSharedMemorySize, EDGE_SMEM);
    cudaFuncSetAttribute(node_mma_kernel, cudaFuncAttributeMaxDynamicSharedMemorySize, NODE_SMEM);

    // ---- sort edges by dst (once; reused by all layers) ----
    cudaMemsetAsync(cnt, 0, 50048 * sizeof(int), 0);
    hist_kernel<<<592, 256>>>(ei, cnt, nE, nN);
    scan_kernel<<<1, 1024>>>(cnt, offs, nN);
    scatter_kernel<<<592, 256>>>(ei, offs, sSrc, sDst, nE, nN);

    const int edgeBlocks = 148 * 2;   // 2 blocks/SM
    float* bufs[2] = {X1, X2};

    const float* cur = x_in;
    for (int l = 0; l < L; l++) {
        node_mma_kernel<<<dim3(74, 2), 256, NODE_SMEM>>>(
            cur, W1 + (size_t)l * 2 * H * H, b1 + (size_t)l * H, A, Bm, nN);
        float* y = bufs[l & 1];
        cudaMemsetAsync(y, 0xFF, (size_t)nN * H * sizeof(float), 0);  // NaN init
        edge_mma_kernel<<<edgeBlocks, 128, EDGE_SMEM>>>(
            A, Bm, W2 + (size_t)l * H * H, b2 + (size_t)l * H, sSrc, sDst, y, nwork);
        cur = y;
    }
    final_kernel<<<(nN + 7) / 8, 256>>>(cur, Wf, bf, out, nN);
}

// round 17
// speedup vs baseline: 1.1610x; 1.0302x over previous
#include <cuda_runtime.h>
#include <cuda_bf16.h>
#include <cstdint>

#define H 128
#define MAXN 50000
#define NBUF ((size_t)MAXN * H)
#define MAXWORK 851968            // >= E + N

#define HP 132    // H-tile pitch (words): %32==4 -> A-frag LDS conflict-free
#define WP 136    // W pitch (words) node kernel: %32==8 -> B-frag conflict-free
#define WPP 264   // paired-W2 pitch: %32==8 -> LDS.64 conflict-free
#define WTILE 16  // edges per warp-tile
#define EDGE_WARPS 12
#define EDGE_THREADS (EDGE_WARPS * 32)
#define W2P_WORDS (16 * 4 * WPP)                               // 67.6KB
#define EDGE_SMEM ((W2P_WORDS + EDGE_WARPS * WTILE * HP) * 4)  // ~169KB -> 1 block/SM, 12 warps
#define NODE_SMEM ((2 * 128 * WP + 2 * 64 * HP) * 4)           // ~206.8KB

// float scratch: X1, X2 (ping-pong), A, B (per-node partial GEMMs)
__device__ float4 g_scratch4[4 * NBUF / 4];
// int scratch: cnt[50048] | offs[50048] | sortedSrc[MAXWORK] | sortedDst[MAXWORK]
__device__ int g_iscratch[2 * 50048 + 2 * MAXWORK];

__device__ __forceinline__ void atomicMaxF(float* addr, float v) {
    if (v >= 0.f) atomicMax((int*)addr, __float_as_int(v));
    else          atomicMin((unsigned int*)addr, __float_as_uint(v));
}

__device__ __forceinline__ float tf32r(float x) {
    uint32_t u;
    asm("cvt.rna.tf32.f32 %0, %1;" : "=r"(u) : "f"(x));
    return __uint_as_float(u);
}

__device__ __forceinline__ void prefetchL1(const void* p) {
    asm volatile("prefetch.global.L1 [%0];" :: "l"(p));
}

#define MMA_TF32(acc, a0, a1, a2, a3, b0, b1)                                   \
    asm("mma.sync.aligned.m16n8k8.row.col.f32.tf32.tf32.f32 "                   \
        "{%0,%1,%2,%3}, {%4,%5,%6,%7}, {%8,%9}, {%0,%1,%2,%3};"                 \
        : "+f"(acc[0]), "+f"(acc[1]), "+f"(acc[2]), "+f"(acc[3])                \
        : "r"(a0), "r"(a1), "r"(a2), "r"(a3), "r"(b0), "r"(b1))

// ---------------------------------------------------------------------------
// Sorting (counting sort by dst). Runs once per launch, reused by all layers.
// ---------------------------------------------------------------------------
__global__ void hist_kernel(const int* __restrict__ ei, int* __restrict__ cnt,
                            int nE, int nN)
{
    const int nwork = nE + nN;
    for (int e = blockIdx.x * blockDim.x + threadIdx.x; e < nwork;
         e += gridDim.x * blockDim.x) {
        const int d = (e < nE) ? ei[nE + e] : (e - nE);
        atomicAdd(&cnt[d], 1);
    }
}

__global__ void __launch_bounds__(1024) scan_kernel(
    const int* __restrict__ cnt, int* __restrict__ offs, int nN)
{
    __shared__ int sums[1024];
    const int t = threadIdx.x;
    const int chunk = (nN + 1023) / 1024;
    const int lo = t * chunk;
    const int hi = min(lo + chunk, nN);
    int s = 0;
    for (int i = lo; i < hi; i++) s += cnt[i];
    sums[t] = s;
    __syncthreads();
    for (int off = 1; off < 1024; off <<= 1) {
        int v = (t >= off) ? sums[t - off] : 0;
        __syncthreads();
        sums[t] += v;
        __syncthreads();
    }
    int run = sums[t] - s;   // exclusive prefix
    for (int i = lo; i < hi; i++) {
        offs[i] = run;
        run += cnt[i];
    }
}

__global__ void scatter_kernel(const int* __restrict__ ei, int* __restrict__ offs,
                               int* __restrict__ sSrc, int* __restrict__ sDst,
                               int nE, int nN)
{
    const int nwork = nE + nN;
    for (int e = blockIdx.x * blockDim.x + threadIdx.x; e < nwork;
         e += gridDim.x * blockDim.x) {
        int s, d;
        if (e < nE) { s = ei[e]; d = ei[nE + e]; }
        else        { s = d = e - nE; }
        const int pos = atomicAdd(&offs[d], 1);
        sSrc[pos] = s;
        sDst[pos] = d;
    }
}

// ---------------------------------------------------------------------------
// Node GEMM via tensor cores, 3xTF32 split (fp32-accurate). R10 proven shape:
// 256 threads (8 warps), warp grid 2(M)x4(N), M=64 tiles, 2 syncs per tile.
// ---------------------------------------------------------------------------
__global__ void __launch_bounds__(256) node_mma_kernel(
    const float* __restrict__ x, const float* __restrict__ W1l,
    const float* __restrict__ b1l, float* __restrict__ A, float* __restrict__ Bm,
    int nN)
{
    extern __shared__ float sm[];
    float* Wh = sm;                  // [128][WP]
    float* Wl = sm + 128 * WP;       // [128][WP]
    float* Xh = sm + 2 * 128 * WP;   // [64][HP]
    float* Xl = Xh + 64 * HP;        // [64][HP]

    const int tid  = threadIdx.x;
    const int lane = tid & 31;
    const int wid  = tid >> 5;
    const int mg   = wid >> 2;      // 0..1
    const int ng   = wid & 3;       // 0..3
    const int lr   = lane >> 2;     // 0..7
    const int lc   = lane & 3;      // 0..3
    const int half = blockIdx.y;

    for (int i = tid; i < 128 * 128; i += 256) {
        const int k = i >> 7, j = i & 127;
        float wv = (half == 0)
            ? (W1l[k * H + j] - W1l[(H + k) * H + j])
            : W1l[(H + k) * H + j];
        const float hi = tf32r(wv);
        Wh[k * WP + j] = hi;
        Wl[k * WP + j] = tf32r(wv - hi);
    }

    float2 b1c[4];
    #pragma unroll
    for (int ni = 0; ni < 4; ni++) {
        if (half == 0) b1c[ni] = *(const float2*)(b1l + 32 * ng + 8 * ni + 2 * lc);
        else           b1c[ni] = make_float2(0.f, 0.f);
    }
    float* outP = (half == 0) ? A : Bm;
    __syncthreads();

    const int ntiles = (nN + 63) / 64;
    for (int tile = blockIdx.x; tile < ntiles; tile += gridDim.x) {
        const int n0 = tile * 64;

        for (int i = tid; i < 64 * 32; i += 256) {
            const int r = i >> 5, j4 = (i & 31) * 4;
            float4 v = (n0 + r < nN)
                ? *(const float4*)(x + (size_t)(n0 + r) * H + j4)
                : make_float4(0.f, 0.f, 0.f, 0.f);
            float4 hi4, lo4;
            hi4.x = tf32r(v.x); lo4.x = tf32r(v.x - hi4.x);
            hi4.y = tf32r(v.y); lo4.y = tf32r(v.y - hi4.y);
            hi4.z = tf32r(v.z); lo4.z = tf32r(v.z - hi4.z);
            hi4.w = tf32r(v.w); lo4.w = tf32r(v.w - hi4.w);
            *(float4*)(Xh + r * HP + j4) = hi4;
            *(float4*)(Xl + r * HP + j4) = lo4;
        }
        __syncthreads();

        float acc[2][4][4];
        #pragma unroll
        for (int mi = 0; mi < 2; mi++)
            #pragma unroll
            for (int ni = 0; ni < 4; ni++)
                #pragma unroll
                for (int c = 0; c < 4; c++) acc[mi][ni][c] = 0.f;

        #pragma unroll
        for (int ks = 0; ks < 16; ks++) {
            const int kb = ks * 8;
            uint32_t ah[2][4], al[2][4];
            #pragma unroll
            for (int mi = 0; mi < 2; mi++) {
                const int ro = (32 * mg + 16 * mi + lr) * HP + kb + lc;
                ah[mi][0] = __float_as_uint(Xh[ro]);
                ah[mi][1] = __float_as_uint(Xh[ro + 8 * HP]);
                ah[mi][2] = __float_as_uint(Xh[ro + 4]);
                ah[mi][3] = __float_as_uint(Xh[ro + 8 * HP + 4]);
                al[mi][0] = __float_as_uint(Xl[ro]);
                al[mi][1] = __float_as_uint(Xl[ro + 8 * HP]);
                al[mi][2] = __float_as_uint(Xl[ro + 4]);
                al[mi][3] = __float_as_uint(Xl[ro + 8 * HP + 4]);
            }
            #pragma unroll
            for (int ni = 0; ni < 4; ni++) {
                const int bo = (kb + lc) * WP + 32 * ng + 8 * ni + lr;
                const uint32_t bh0 = __float_as_uint(Wh[bo]);
                const uint32_t bh1 = __float_as_uint(Wh[bo + 4 * WP]);
                const uint32_t bl0 = __float_as_uint(Wl[bo]);
                const uint32_t bl1 = __float_as_uint(Wl[bo + 4 * WP]);
                #pragma unroll
                for (int mi = 0; mi < 2; mi++) {
                    MMA_TF32(acc[mi][ni], ah[mi][0], ah[mi][1], ah[mi][2], ah[mi][3], bh0, bh1);
                    MMA_TF32(acc[mi][ni], al[mi][0], al[mi][1], al[mi][2], al[mi][3], bh0, bh1);
                    MMA_TF32(acc[mi][ni], ah[mi][0], ah[mi][1], ah[mi][2], ah[mi][3], bl0, bl1);
                }
            }
        }
        __syncthreads();

        #pragma unroll
        for (int mi = 0; mi < 2; mi++) {
            const int r0 = 32 * mg + 16 * mi + lr;
            #pragma unroll
            for (int ni = 0; ni < 4; ni++) {
                const int col = 32 * ng + 8 * ni + 2 * lc;
                if (n0 + r0 < nN)
                    *(float2*)(outP + (size_t)(n0 + r0) * H + col) =
                        make_float2(acc[mi][ni][0] + b1c[ni].x, acc[mi][ni][1] + b1c[ni].y);
                if (n0 + r0 + 8 < nN)
                    *(float2*)(outP + (size_t)(n0 + r0 + 8) * H + col) =
                        make_float2(acc[mi][ni][2] + b1c[ni].x, acc[mi][ni][3] + b1c[ni].y);
            }
        }
    }
}

// ---------------------------------------------------------------------------
// Edge kernel v8: ONE 384-thread block per SM (12 warps, 3/SMSP balanced),
// SHARED W2p (paired-k layout), warp-independent 16-edge tiles,
// index double-buffer + L1 row prefetch. No block barriers in the loop.
// ---------------------------------------------------------------------------
__global__ void __launch_bounds__(EDGE_THREADS, 1) edge_mma_kernel(
    const float* __restrict__ A, const float* __restrict__ Bm,
    const float* __restrict__ W2, const float* __restrict__ b2,
    const int* __restrict__ sSrc, const int* __restrict__ sDst,
    float* __restrict__ y, int nwork)
{
    extern __shared__ float sm[];
    float* W2p = sm;                               // [64][WPP]: (ks,lc) -> 128 float2
    const int tid  = threadIdx.x;
    const int lane = tid & 31;
    const int wid  = tid >> 5;                     // 0..11
    float* Hs = sm + W2P_WORDS + wid * (WTILE * HP); // per-warp [16][HP]

    // W2 -> paired layout: W2p[(ks*4+lc)*WPP + 2*col] = (tf32 W2[8ks+lc][col], tf32 W2[8ks+lc+4][col])
    for (int i = tid; i < 64 * 128; i += EDGE_THREADS) {
        const int pr  = i >> 7;        // 0..63
        const int col = i & 127;
        const int k   = (pr >> 2) * 8 + (pr & 3);
        const float v0 = tf32r(W2[k * H + col]);
        const float v1 = tf32r(W2[(k + 4) * H + col]);
        *(float2*)(W2p + pr * WPP + 2 * col) = make_float2(v0, v1);
    }
    const float4 b2c = *(const float4*)(b2 + lane * 4);
    __syncthreads();   // only barrier: W2p ready

    const int lr   = lane >> 2;     // 0..7
    const int lc   = lane & 3;      // 0..3
    const int eL   = lane >> 1;     // 0..15 : my build row
    const int half = lane & 1;      // 0..1  : column half

    const int ntiles = (nwork + WTILE - 1) / WTILE;
    const int gw     = blockIdx.x * EDGE_WARPS + wid;
    const int stride = gridDim.x * EDGE_WARPS;

    // preload first tile's indices
    int tile = gw;
    int s = -1, d = -1;
    if (tile < ntiles) {
        const int e = tile * WTILE + eL;
        if (e < nwork) { s = sSrc[e]; d = sDst[e]; }
    }

    while (tile < ntiles) {
        const int nextTile = tile + stride;

        // kick next tile's index loads early (needed ~2000 cyc from now)
        int sN = -1, dN = -1;
        if (nextTile < ntiles) {
            const int e = nextTile * WTILE + eL;
            if (e < nwork) { sN = sSrc[e]; dN = sDst[e]; }
        }

        // ---- build: lane = (row eL, half) -> 64 cols ----
        {
            float* hrow = Hs + eL * HP + half * 64;
            if (d >= 0) {
                const float4* ap = (const float4*)(A  + (size_t)d * H + half * 64);
                const float4* bp = (const float4*)(Bm + (size_t)s * H + half * 64);
                #pragma unroll
                for (int i = 0; i < 16; i++) {
                    const float4 a = ap[i], b = bp[i];
                    float4 hh;
                    hh.x = tf32r(fmaxf(a.x + b.x, 0.f));
                    hh.y = tf32r(fmaxf(a.y + b.y, 0.f));
                    hh.z = tf32r(fmaxf(a.z + b.z, 0.f));
                    hh.w = tf32r(fmaxf(a.w + b.w, 0.f));
                    *(float4*)(hrow + i * 4) = hh;
                }
            } else {
                #pragma unroll
                for (int i = 0; i < 16; i++)
                    *(float4*)(hrow + i * 4) = make_float4(0.f, 0.f, 0.f, 0.f);
            }
        }
        __syncwarp();

        // ---- mma: m16 x n128 x k128, B via LDS.64 paired loads ----
        float acc[16][4];
        #pragma unroll
        for (int ni = 0; ni < 16; ni++)
            #pragma unroll
            for (int c = 0; c < 4; c++) acc[ni][c] = 0.f;

        #pragma unroll
        for (int ks = 0; ks < 16; ks++) {
            const int kb = ks * 8;
            const float* ab = Hs + lr * HP + kb + lc;
            const uint32_t a0 = __float_as_uint(ab[0]);
            const uint32_t a1 = __float_as_uint(ab[8 * HP]);
            const uint32_t a2 = __float_as_uint(ab[4]);
            const uint32_t a3 = __float_as_uint(ab[8 * HP + 4]);
            const float* bbase = W2p + (ks * 4 + lc) * WPP + 2 * lr;
            #pragma unroll
            for (int ni = 0; ni < 16; ni++) {
                const float2 bp = *(const float2*)(bbase + 16 * ni);
                MMA_TF32(acc[ni], a0, a1, a2, a3,
                         __float_as_uint(bp.x), __float_as_uint(bp.y));
            }
        }
        __syncwarp();   // frag reads done before writeback overwrites Hs

        // ---- writeback raw acc into Hs ----
        #pragma unroll
        for (int ni = 0; ni < 16; ni++) {
            const int col = 8 * ni + 2 * lc;
            *(float2*)(Hs + lr * HP + col)       = make_float2(acc[ni][0], acc[ni][1]);
            *(float2*)(Hs + (lr + 8) * HP + col) = make_float2(acc[ni][2], acc[ni][3]);
        }

        // ---- prefetch next tile's gather rows into L1 (covers reduce latency) ----
        if (dN >= 0) {
            const char* ap = (const char*)(A  + (size_t)dN * H + half * 64);
            const char* bp = (const char*)(Bm + (size_t)sN * H + half * 64);
            prefetchL1(ap); prefetchL1(ap + 128);
            prefetchL1(bp); prefetchL1(bp + 128);
        }
        __syncwarp();

        // ---- segmented max over 16 sorted rows; lane = 4 cols; b2 folded ----
        {
            int cur_d = -1;
            float4 m = make_float4(0.f, 0.f, 0.f, 0.f);
            #pragma unroll
            for (int r = 0; r < 16; r++) {
                const int dr = __shfl_sync(0xFFFFFFFFu, d, 2 * r);
                const float4 v = *(const float4*)(Hs + r * HP + lane * 4);
                if (dr != cur_d) {
                    if (cur_d >= 0) {
                        float* yr = y + (size_t)cur_d * H + lane * 4;
                        atomicMaxF(yr + 0, m.x + b2c.x);
                        atomicMaxF(yr + 1, m.y + b2c.y);
                        atomicMaxF(yr + 2, m.z + b2c.z);
                        atomicMaxF(yr + 3, m.w + b2c.w);
                    }
                    cur_d = dr;
                    m = v;
                } else {
                    m.x = fmaxf(m.x, v.x); m.y = fmaxf(m.y, v.y);
                    m.z = fmaxf(m.z, v.z); m.w = fmaxf(m.w, v.w);
                }
            }
            if (cur_d >= 0) {
                float* yr = y + (size_t)cur_d * H + lane * 4;
                atomicMaxF(yr + 0, m.x + b2c.x);
                atomicMaxF(yr + 1, m.y + b2c.y);
                atomicMaxF(yr + 2, m.z + b2c.z);
                atomicMaxF(yr + 3, m.w + b2c.w);
            }
        }
        __syncwarp();   // reduce reads done before next build overwrites Hs

        s = sN; d = dN; tile = nextTile;
    }
}

// ---------------------------------------------------------------------------
// Final: out[n] = x[n] @ Wf + bf   (H=128 -> D=3). Warp per node.
// ---------------------------------------------------------------------------
__global__ void __launch_bounds__(256) final_kernel(
    const float* __restrict__ x, const float* __restrict__ Wf,
    const float* __restrict__ bf, float* __restrict__ out, int nN)
{
    __shared__ float Wfs[H * 3];
    const int tid = threadIdx.x;
    for (int i = tid; i < H * 3; i += 256) Wfs[i] = Wf[i];
    __syncthreads();

    const int lane = tid & 31;
    const int node = blockIdx.x * 8 + (tid >> 5);
    if (node >= nN) return;

    const float4 xv = *(const float4*)(x + (size_t)node * H + lane * 4);
    float s0 = 0.f, s1 = 0.f, s2 = 0.f;
    const float xt[4] = {xv.x, xv.y, xv.z, xv.w};
    #pragma unroll
    for (int t = 0; t < 4; t++) {
        const int k = lane * 4 + t;
        s0 = fmaf(xt[t], Wfs[k * 3 + 0], s0);
        s1 = fmaf(xt[t], Wfs[k * 3 + 1], s1);
        s2 = fmaf(xt[t], Wfs[k * 3 + 2], s2);
    }
    #pragma unroll
    for (int off = 16; off > 0; off >>= 1) {
        s0 += __shfl_down_sync(0xFFFFFFFFu, s0, off);
        s1 += __shfl_down_sync(0xFFFFFFFFu, s1, off);
        s2 += __shfl_down_sync(0xFFFFFFFFu, s2, off);
    }
    if (lane == 0) {
        out[(size_t)node * 3 + 0] = s0 + bf[0];
        out[(size_t)node * 3 + 1] = s1 + bf[1];
        out[(size_t)node * 3 + 2] = s2 + bf[2];
    }
}

// ---------------------------------------------------------------------------
extern "C" void kernel_launch(void* const* d_in, const int* in_sizes, int n_in,
                              void* d_out, int out_size)
{
    const float*      x_in = (const float*)d_in[0];
    const int*        ei   = (const int*)d_in[1];
    const float*      W1   = (const float*)d_in[2];
    const float*      b1   = (const float*)d_in[3];
    const float*      W2   = (const float*)d_in[4];
    const float*      b2   = (const float*)d_in[5];
    const float*      Wf   = (const float*)d_in[6];
    const float*      bf   = (const float*)d_in[7];
    float*            out  = (float*)d_out;

    const int nN = in_sizes[0] / H;          // 50000
    const int nE = in_sizes[1] / 2;          // 800000
    const int L  = in_sizes[3] / H;          // 4
    const int nwork = nE + nN;

    void* base = nullptr;
    cudaGetSymbolAddress(&base, g_scratch4);
    float* X1 = (float*)base;
    float* X2 = X1 + NBUF;
    float* A  = X1 + 2 * NBUF;
    float* Bm = X1 + 3 * NBUF;

    void* ibase = nullptr;
    cudaGetSymbolAddress(&ibase, g_iscratch);
    int* cnt  = (int*)ibase;
    int* offs = cnt + 50048;
    int* sSrc = cnt + 2 * 50048;
    int* sDst = sSrc + MAXWORK;

    cudaFuncSetAttribute(edge_mma_kernel, cudaFuncAttributeMaxDynamicSharedMemorySize, EDGE_SMEM);
    cudaFuncSetAttribute(node_mma_kernel, cudaFuncAttributeMaxDynamicSharedMemorySize, NODE_SMEM);

    // ---- sort edges by dst (once; reused by all layers) ----
    cudaMemsetAsync(cnt, 0, 50048 * sizeof(int), 0);
    hist_kernel<<<592, 256>>>(ei, cnt, nE, nN);
    scan_kernel<<<1, 1024>>>(cnt, offs, nN);
    scatter_kernel<<<592, 256>>>(ei, offs, sSrc, sDst, nE, nN);

    float* bufs[2] = {X1, X2};

    const float* cur = x_in;
    for (int l = 0; l < L; l++) {
        node_mma_kernel<<<dim3(74, 2), 256, NODE_SMEM>>>(
            cur, W1 + (size_t)l * 2 * H * H, b1 + (size_t)l * H, A, Bm, nN);
        float* y = bufs[l & 1];
        cudaMemsetAsync(y, 0xFF, (size_t)nN * H * sizeof(float), 0);  // NaN init
        edge_mma_kernel<<<148, EDGE_THREADS, EDGE_SMEM>>>(
            A, Bm, W2 + (size_t)l * H * H, b2 + (size_t)l * H, sSrc, sDst, y, nwork);
        cur = y;
    }
    final_kernel<<<(nN + 7) / 8, 256>>>(cur, Wf, bf, out, nN);
}